// round 1
// baseline (speedup 1.0000x reference)
#include <cuda_runtime.h>
#include <math.h>

// ---------------------------------------------------------------------------
// Problem constants
// ---------------------------------------------------------------------------
#define BB    8
#define SS    512
#define DD    512
#define HH    64
#define DK    8
#define WID   16
#define NN    (SS + 2 * WID)      // 544
#define MQ    (BB * NN)           // 4352  (multiple of 128)
#define MH    (BB * SS)           // 4096  (multiple of 128)
#define KDIM  512
#define WINSZ (WID + 2)           // 18 positions in the band

// ---------------------------------------------------------------------------
// Scratch (static device memory; allocation is forbidden)
// ---------------------------------------------------------------------------
__device__ float g_X[MQ * DD];                 // padded input [B*N, D]
__device__ float g_QKV0[MQ * 3 * DD];          // left  qkv [B*N, 1536]
__device__ float g_QKV1[MQ * 3 * DD];          // right qkv
__device__ float g_ATT0[MQ * DD];
__device__ float g_ATT1[MQ * DD];
__device__ float g_PROJ0[MQ * DD];
__device__ float g_PROJ1[MQ * DD];
__device__ float g_HX0[MH * DD];
__device__ float g_HX1[MH * DD];
__device__ float g_HP[MH * 2 * DD];            // highway projection scratch (reused)

// ---------------------------------------------------------------------------
// Kernel 0: build padded input  X[b, n, :] = left_pad / inputs / right_pad
// ---------------------------------------------------------------------------
__global__ void pad_kernel(const float* __restrict__ inp,
                           const float* __restrict__ lp,
                           const float* __restrict__ rp,
                           float* __restrict__ X) {
    int t = blockIdx.x * blockDim.x + threadIdx.x;     // float4 index
    const int TOT = MQ * (DD / 4);
    if (t >= TOT) return;
    int row = t / (DD / 4);
    int c4  = t % (DD / 4);
    int b = row / NN;
    int n = row % NN;
    float4 v;
    if (n < WID) {
        v = reinterpret_cast<const float4*>(lp)[n * (DD / 4) + c4];
    } else if (n >= WID + SS) {
        v = reinterpret_cast<const float4*>(rp)[(n - WID - SS) * (DD / 4) + c4];
    } else {
        v = reinterpret_cast<const float4*>(inp)[((size_t)b * SS + (n - WID)) * (DD / 4) + c4];
    }
    reinterpret_cast<float4*>(X)[t] = v;
}

// ---------------------------------------------------------------------------
// SGEMM:  C[M, Nt] = A[M, 512] @ W[Nt, 512]^T + bias[Nt]
// 128x128 tile, BK=8, 256 threads, 8x8 micro-tile. M, Nt multiples of 128.
// ---------------------------------------------------------------------------
__global__ __launch_bounds__(256, 2) void gemm_bias_kernel(
    const float* __restrict__ A, const float* __restrict__ W,
    const float* __restrict__ bias, float* __restrict__ C, int Nt) {
    __shared__ float As[8][128];
    __shared__ float Ws[8][128];

    const int bm = blockIdx.y * 128;
    const int bn = blockIdx.x * 128;
    const int tid = threadIdx.x;
    const int tx = tid & 15;        // 0..15 -> N micro
    const int ty = tid >> 4;        // 0..15 -> M micro
    const int lr = tid >> 1;        // 0..127 row within tile for loads
    const int lc = (tid & 1) * 4;   // 0 or 4

    const float* Ap = A + (size_t)(bm + lr) * KDIM + lc;
    const float* Wp = W + (size_t)(bn + lr) * KDIM + lc;

    float acc[8][8];
#pragma unroll
    for (int i = 0; i < 8; i++)
#pragma unroll
        for (int j = 0; j < 8; j++) acc[i][j] = 0.0f;

    for (int k0 = 0; k0 < KDIM; k0 += 8) {
        float4 av = *reinterpret_cast<const float4*>(Ap + k0);
        float4 wv = *reinterpret_cast<const float4*>(Wp + k0);
        As[lc + 0][lr] = av.x; As[lc + 1][lr] = av.y;
        As[lc + 2][lr] = av.z; As[lc + 3][lr] = av.w;
        Ws[lc + 0][lr] = wv.x; Ws[lc + 1][lr] = wv.y;
        Ws[lc + 2][lr] = wv.z; Ws[lc + 3][lr] = wv.w;
        __syncthreads();
#pragma unroll
        for (int kk = 0; kk < 8; kk++) {
            float a[8], b[8];
#pragma unroll
            for (int i = 0; i < 8; i++) a[i] = As[kk][ty * 8 + i];
#pragma unroll
            for (int j = 0; j < 8; j++) b[j] = Ws[kk][tx * 8 + j];
#pragma unroll
            for (int i = 0; i < 8; i++)
#pragma unroll
                for (int j = 0; j < 8; j++)
                    acc[i][j] = fmaf(a[i], b[j], acc[i][j]);
        }
        __syncthreads();
    }

    float bb[8];
#pragma unroll
    for (int j = 0; j < 8; j++) bb[j] = bias[bn + tx * 8 + j];

#pragma unroll
    for (int i = 0; i < 8; i++) {
        float* crow = C + (size_t)(bm + ty * 8 + i) * Nt + bn + tx * 8;
        float4 o0, o1;
        o0.x = acc[i][0] + bb[0]; o0.y = acc[i][1] + bb[1];
        o0.z = acc[i][2] + bb[2]; o0.w = acc[i][3] + bb[3];
        o1.x = acc[i][4] + bb[4]; o1.y = acc[i][5] + bb[5];
        o1.z = acc[i][6] + bb[6]; o1.w = acc[i][7] + bb[7];
        reinterpret_cast<float4*>(crow)[0] = o0;
        reinterpret_cast<float4*>(crow)[1] = o1;
    }
}

// ---------------------------------------------------------------------------
// Banded window attention. One block per (b, i), one thread per head.
// QKV layout: [B*N, 1536]  (cols 0..511 = Q, 512..1023 = K, 1024..1535 = V)
// left:  j in [i-17, i] ; right: j in [i, i+17]   (clipped to [0, N-1])
// ---------------------------------------------------------------------------
__global__ void attn_kernel(const float* __restrict__ QKV,
                            float* __restrict__ out, int is_right) {
    const int bi = blockIdx.x;         // 0..MQ-1
    const int b = bi / NN;
    const int i = bi % NN;
    const int h = threadIdx.x;         // 0..63

    const float4* qv = reinterpret_cast<const float4*>(QKV + (size_t)bi * 1536 + h * 8);
    const float4 q0 = qv[0], q1 = qv[1];

    const int j0 = is_right ? i : (i - WID - 1);

    float sc[WINSZ];
    float mx = -1e30f;
#pragma unroll
    for (int t = 0; t < WINSZ; t++) {
        int j = j0 + t;
        bool valid = (j >= 0) && (j < NN);
        int jc = min(max(j, 0), NN - 1);
        const float4* kv = reinterpret_cast<const float4*>(
            QKV + ((size_t)(b * NN + jc)) * 1536 + 512 + h * 8);
        float4 k0 = kv[0], k1 = kv[1];
        float s = q0.x * k0.x + q0.y * k0.y + q0.z * k0.z + q0.w * k0.w +
                  q1.x * k1.x + q1.y * k1.y + q1.z * k1.z + q1.w * k1.w;
        s *= 0.35355339059327373f;   // 1/sqrt(8)
        sc[t] = valid ? s : -1e30f;
        mx = fmaxf(mx, sc[t]);
    }
    float sum = 0.0f;
#pragma unroll
    for (int t = 0; t < WINSZ; t++) {
        sc[t] = expf(sc[t] - mx);
        sum += sc[t];
    }
    const float inv = 1.0f / sum;

    float4 a0 = make_float4(0.f, 0.f, 0.f, 0.f);
    float4 a1 = make_float4(0.f, 0.f, 0.f, 0.f);
#pragma unroll
    for (int t = 0; t < WINSZ; t++) {
        int j = j0 + t;
        int jc = min(max(j, 0), NN - 1);
        const float4* vv = reinterpret_cast<const float4*>(
            QKV + ((size_t)(b * NN + jc)) * 1536 + 1024 + h * 8);
        float4 v0 = vv[0], v1 = vv[1];
        float p = sc[t] * inv;
        a0.x += p * v0.x; a0.y += p * v0.y; a0.z += p * v0.z; a0.w += p * v0.w;
        a1.x += p * v1.x; a1.y += p * v1.y; a1.z += p * v1.z; a1.w += p * v1.w;
    }
    float4* op = reinterpret_cast<float4*>(out + (size_t)bi * DD + h * 8);
    op[0] = a0;
    op[1] = a1;
}

// ---------------------------------------------------------------------------
// Slice rows [WIDTH : WIDTH+S] of the [B*N, D] tensor into [B*S, D]
// ---------------------------------------------------------------------------
__global__ void copy_slice_kernel(const float* __restrict__ src,
                                  float* __restrict__ dst) {
    int t = blockIdx.x * blockDim.x + threadIdx.x;    // float4 index
    const int TOT = MH * (DD / 4);
    if (t >= TOT) return;
    int r = t / (DD / 4);
    int c4 = t % (DD / 4);
    int b = r / SS;
    int s = r % SS;
    reinterpret_cast<float4*>(dst)[t] =
        reinterpret_cast<const float4*>(src)[((size_t)(b * NN + WID + s)) * (DD / 4) + c4];
}

// ---------------------------------------------------------------------------
// Highway elementwise: x = sigmoid(hp[:,D:]) * x + (1 - sigmoid) * relu(hp[:,:D])
// ---------------------------------------------------------------------------
__global__ void highway_ew_kernel(float* __restrict__ x,
                                  const float* __restrict__ hp) {
    int idx = blockIdx.x * blockDim.x + threadIdx.x;
    const int TOT = MH * DD;
    if (idx >= TOT) return;
    int r = idx / DD;
    int c = idx % DD;
    float p = hp[(size_t)r * (2 * DD) + c];
    float g = hp[(size_t)r * (2 * DD) + DD + c];
    float nl = fmaxf(p, 0.0f);
    float gate = 1.0f / (1.0f + expf(-g));
    x[idx] = gate * x[idx] + (1.0f - gate) * nl;
}

// ---------------------------------------------------------------------------
// Output: last = concat(left, right) on feature dim. Tuple is (last[None], last)
// -> identical data twice; second copy guarded by out_size.
// ---------------------------------------------------------------------------
__global__ void write_out_kernel(const float* __restrict__ hl,
                                 const float* __restrict__ hr,
                                 float* __restrict__ out, int out_size) {
    int t = blockIdx.x * blockDim.x + threadIdx.x;     // float4 index
    const int TOT4 = MH * (2 * DD / 4);                // 4096 * 256
    if (t >= TOT4) return;
    int r = t >> 8;            // row (b*S+s)
    int c4 = t & 255;          // float4 col within 1024
    float4 v = (c4 < 128)
        ? reinterpret_cast<const float4*>(hl)[r * 128 + c4]
        : reinterpret_cast<const float4*>(hr)[r * 128 + (c4 - 128)];
    reinterpret_cast<float4*>(out)[t] = v;
    long long second = (long long)(t + TOT4) * 4 + 3;
    if (second < (long long)out_size)
        reinterpret_cast<float4*>(out)[t + TOT4] = v;
}

// ---------------------------------------------------------------------------
// Launch
// ---------------------------------------------------------------------------
extern "C" void kernel_launch(void* const* d_in, const int* in_sizes, int n_in,
                              void* d_out, int out_size) {
    const float* inputs    = (const float*)d_in[0];
    const float* left_pad  = (const float*)d_in[1];
    const float* right_pad = (const float*)d_in[2];
    const float* l_Wqkv    = (const float*)d_in[3];
    const float* l_bqkv    = (const float*)d_in[4];
    const float* l_Wo      = (const float*)d_in[5];
    const float* l_bo      = (const float*)d_in[6];
    const float* r_Wqkv    = (const float*)d_in[7];
    const float* r_bqkv    = (const float*)d_in[8];
    const float* r_Wo      = (const float*)d_in[9];
    const float* r_bo      = (const float*)d_in[10];
    const float* lhw_W     = (const float*)d_in[11];
    const float* lhw_b     = (const float*)d_in[12];
    const float* rhw_W     = (const float*)d_in[13];
    const float* rhw_b     = (const float*)d_in[14];
    float* out = (float*)d_out;

    float *pX, *pQKV0, *pQKV1, *pATT0, *pATT1, *pPROJ0, *pPROJ1, *pHX0, *pHX1, *pHP;
    cudaGetSymbolAddress((void**)&pX,    g_X);
    cudaGetSymbolAddress((void**)&pQKV0, g_QKV0);
    cudaGetSymbolAddress((void**)&pQKV1, g_QKV1);
    cudaGetSymbolAddress((void**)&pATT0, g_ATT0);
    cudaGetSymbolAddress((void**)&pATT1, g_ATT1);
    cudaGetSymbolAddress((void**)&pPROJ0, g_PROJ0);
    cudaGetSymbolAddress((void**)&pPROJ1, g_PROJ1);
    cudaGetSymbolAddress((void**)&pHX0,  g_HX0);
    cudaGetSymbolAddress((void**)&pHX1,  g_HX1);
    cudaGetSymbolAddress((void**)&pHP,   g_HP);

    // 1) padded input
    {
        int tot = MQ * (DD / 4);
        pad_kernel<<<(tot + 255) / 256, 256>>>(inputs, left_pad, right_pad, pX);
    }

    const float* Wqkv[2] = {l_Wqkv, r_Wqkv};
    const float* bqkv[2] = {l_bqkv, r_bqkv};
    const float* Wo[2]   = {l_Wo, r_Wo};
    const float* bo[2]   = {l_bo, r_bo};
    const float* hwW[2]  = {lhw_W, rhw_W};
    const float* hwB[2]  = {lhw_b, rhw_b};
    float* QKV[2]  = {pQKV0, pQKV1};
    float* ATT[2]  = {pATT0, pATT1};
    float* PROJ[2] = {pPROJ0, pPROJ1};
    float* HX[2]   = {pHX0, pHX1};

    for (int side = 0; side < 2; side++) {
        // QKV projection: [4352,512] @ [1536,512]^T
        gemm_bias_kernel<<<dim3((3 * DD) / 128, MQ / 128), 256>>>(
            pX, Wqkv[side], bqkv[side], QKV[side], 3 * DD);

        // windowed attention
        attn_kernel<<<MQ, HH>>>(QKV[side], ATT[side], side);

        // output projection: [4352,512] @ [512,512]^T
        gemm_bias_kernel<<<dim3(DD / 128, MQ / 128), 256>>>(
            ATT[side], Wo[side], bo[side], PROJ[side], DD);

        // slice [WIDTH : WIDTH+S]
        {
            int tot = MH * (DD / 4);
            copy_slice_kernel<<<(tot + 255) / 256, 256>>>(PROJ[side], HX[side]);
        }

        // 2 highway layers
        for (int l = 0; l < 2; l++) {
            gemm_bias_kernel<<<dim3((2 * DD) / 128, MH / 128), 256>>>(
                HX[side], hwW[side] + (size_t)l * (2 * DD) * DD,
                hwB[side] + (size_t)l * (2 * DD), pHP, 2 * DD);
            int tot = MH * DD;
            highway_ew_kernel<<<(tot + 255) / 256, 256>>>(HX[side], pHP);
        }
    }

    // final concat + duplicate write (all_layers, last)
    {
        int tot4 = MH * (2 * DD / 4);
        write_out_kernel<<<(tot4 + 255) / 256, 256>>>(pHX0, pHX1, out, out_size);
    }
}

// round 4
// speedup vs baseline: 2.3021x; 2.3021x over previous
#include <cuda_runtime.h>
#include <cstdint>
#include <math.h>

// ---------------------------------------------------------------------------
// Problem constants
// ---------------------------------------------------------------------------
#define BB    8
#define SS    512
#define DD    512
#define HH    64
#define WID   16
#define NN    (SS + 2 * WID)      // 544
#define MQ    (BB * NN)           // 4352
#define MH    (BB * SS)           // 4096
#define KDIM  512
#define WINSZ (WID + 2)           // 18

// ---------------------------------------------------------------------------
// Scratch (static device memory; allocation is forbidden)
// ---------------------------------------------------------------------------
__device__ float g_X[MQ * DD];                 // padded input, tf32-rounded
__device__ float g_QKV0[MQ * 3 * DD];
__device__ float g_QKV1[MQ * 3 * DD];
__device__ float g_ATT0[MQ * DD];
__device__ float g_ATT1[MQ * DD];
__device__ float g_PROJ0[MQ * DD];
__device__ float g_PROJ1[MQ * DD];
__device__ float g_HX0[MH * DD];
__device__ float g_HX1[MH * DD];
__device__ float g_HP[MH * 2 * DD];
// converted (tf32-rounded) weights, packed:
//  [0]        l_Wqkv  1536*512 = 786432
//  [786432]   r_Wqkv
//  [1572864]  l_Wo     512*512 = 262144
//  [1835008]  r_Wo
//  [2097152]  lhw_W   2*1024*512 = 1048576
//  [3145728]  rhw_W
__device__ float g_WC[4194304];

// ---------------------------------------------------------------------------
// tf32 rounding helper (round-to-nearest via cvt.rna)
// ---------------------------------------------------------------------------
__device__ __forceinline__ float rtf32(float x) {
    uint32_t r;
    asm("cvt.rna.tf32.f32 %0, %1;" : "=r"(r) : "f"(x));
    return __uint_as_float(r);
}
__device__ __forceinline__ float4 rtf32_4(float4 v) {
    v.x = rtf32(v.x); v.y = rtf32(v.y); v.z = rtf32(v.z); v.w = rtf32(v.w);
    return v;
}

// ---------------------------------------------------------------------------
// Convert all weight tensors to tf32-rounded fp32 (packed into g_WC)
// ---------------------------------------------------------------------------
__global__ void convert_weights_kernel(const float* __restrict__ w0,
                                       const float* __restrict__ w1,
                                       const float* __restrict__ w2,
                                       const float* __restrict__ w3,
                                       const float* __restrict__ w4,
                                       const float* __restrict__ w5,
                                       float* __restrict__ out) {
    // float4 boundaries (total 1048576 float4s)
    const int b0 = 196608, b1 = 393216, b2 = 458752, b3 = 524288, b4 = 786432,
              b5 = 1048576;
    int t = blockIdx.x * blockDim.x + threadIdx.x;
    if (t >= b5) return;
    const float* src;
    int loc;
    if (t < b0)      { src = w0; loc = t; }
    else if (t < b1) { src = w1; loc = t - b0; }
    else if (t < b2) { src = w2; loc = t - b1; }
    else if (t < b3) { src = w3; loc = t - b2; }
    else if (t < b4) { src = w4; loc = t - b3; }
    else             { src = w5; loc = t - b4; }
    float4 v = reinterpret_cast<const float4*>(src)[loc];
    reinterpret_cast<float4*>(out)[t] = rtf32_4(v);
}

// ---------------------------------------------------------------------------
// Build padded input (tf32-rounded): X[b,n,:] = left_pad / inputs / right_pad
// ---------------------------------------------------------------------------
__global__ void pad_kernel(const float* __restrict__ inp,
                           const float* __restrict__ lp,
                           const float* __restrict__ rp,
                           float* __restrict__ X) {
    int t = blockIdx.x * blockDim.x + threadIdx.x;
    const int TOT = MQ * (DD / 4);
    if (t >= TOT) return;
    int row = t / (DD / 4);
    int c4  = t % (DD / 4);
    int b = row / NN;
    int n = row % NN;
    float4 v;
    if (n < WID) {
        v = reinterpret_cast<const float4*>(lp)[n * (DD / 4) + c4];
    } else if (n >= WID + SS) {
        v = reinterpret_cast<const float4*>(rp)[(n - WID - SS) * (DD / 4) + c4];
    } else {
        v = reinterpret_cast<const float4*>(inp)[((size_t)b * SS + (n - WID)) * (DD / 4) + c4];
    }
    reinterpret_cast<float4*>(X)[t] = rtf32_4(v);
}

// ---------------------------------------------------------------------------
// TF32 tensor-core GEMM: C[M, Nt] = A[M, 512] @ W[Nt, 512]^T + bias[Nt]
// 128x128 tile, BK=32, 256 threads (8 warps, each 64m x 32n), cp.async
// double buffering. A and W must be pre-rounded to tf32 values.
// ---------------------------------------------------------------------------
#define STRIDE      36
#define TILE_WORDS  (128 * STRIDE)        // 4608
#define STAGE_WORDS (2 * TILE_WORDS)      // 9216
#define GEMM_SMEM   (2 * STAGE_WORDS * 4) // 73728 bytes

__global__ __launch_bounds__(256) void gemm_tf32_kernel(
    const float* __restrict__ A, const float* __restrict__ W,
    const float* __restrict__ bias, float* __restrict__ C, int Nt) {
    extern __shared__ uint32_t sm[];

    const int bm = blockIdx.y * 128;
    const int bn = blockIdx.x * 128;
    const int tid = threadIdx.x;
    const int lane = tid & 31;
    const int wrp = tid >> 5;
    const int wm = (wrp & 1) * 64;     // warp m offset
    const int wn = (wrp >> 1) * 32;    // warp n offset
    const int g  = lane >> 2;          // group id 0..7
    const int tg = lane & 3;           // thread-in-group 0..3

    // global->smem copy mapping: 2 threads per row, 4 float4 each
    const int lrow = tid >> 1;         // 0..127
    const int half = tid & 1;          // 0 or 1
    const float* Abase = A + (size_t)(bm + lrow) * KDIM + half * 16;
    const float* Wbase = W + (size_t)(bn + lrow) * KDIM + half * 16;
    const uint32_t dstA =
        (uint32_t)__cvta_generic_to_shared(&sm[lrow * STRIDE + half * 16]);

    float acc[4][4][4];
#pragma unroll
    for (int mt = 0; mt < 4; mt++)
#pragma unroll
        for (int nt = 0; nt < 4; nt++)
#pragma unroll
            for (int r = 0; r < 4; r++) acc[mt][nt][r] = 0.0f;

    auto issue = [&](int s, int k0) {
        uint32_t da = dstA + s * STAGE_WORDS * 4;
        uint32_t dw = da + TILE_WORDS * 4;
        const float* sa = Abase + k0;
        const float* sw = Wbase + k0;
#pragma unroll
        for (int i = 0; i < 4; i++) {
            asm volatile("cp.async.cg.shared.global [%0], [%1], 16;"
                         :: "r"(da + i * 16), "l"(sa + i * 4));
            asm volatile("cp.async.cg.shared.global [%0], [%1], 16;"
                         :: "r"(dw + i * 16), "l"(sw + i * 4));
        }
        asm volatile("cp.async.commit_group;");
    };

    auto compute = [&](int s) {
        const uint32_t* As = sm + s * STAGE_WORDS;
        const uint32_t* Ws = As + TILE_WORDS;
#pragma unroll
        for (int kk = 0; kk < 4; kk++) {
            uint32_t a[4][4], b[4][2];
#pragma unroll
            for (int mt = 0; mt < 4; mt++) {
                int rb = wm + mt * 16;
                a[mt][0] = As[(rb + g) * STRIDE + kk * 8 + tg];
                a[mt][1] = As[(rb + g + 8) * STRIDE + kk * 8 + tg];
                a[mt][2] = As[(rb + g) * STRIDE + kk * 8 + tg + 4];
                a[mt][3] = As[(rb + g + 8) * STRIDE + kk * 8 + tg + 4];
            }
#pragma unroll
            for (int nt = 0; nt < 4; nt++) {
                int cb = wn + nt * 8;
                b[nt][0] = Ws[(cb + g) * STRIDE + kk * 8 + tg];
                b[nt][1] = Ws[(cb + g) * STRIDE + kk * 8 + tg + 4];
            }
#pragma unroll
            for (int mt = 0; mt < 4; mt++)
#pragma unroll
                for (int nt = 0; nt < 4; nt++)
                    asm volatile(
                        "mma.sync.aligned.m16n8k8.row.col.f32.tf32.tf32.f32 "
                        "{%0,%1,%2,%3},{%4,%5,%6,%7},{%8,%9},{%0,%1,%2,%3};"
                        : "+f"(acc[mt][nt][0]), "+f"(acc[mt][nt][1]),
                          "+f"(acc[mt][nt][2]), "+f"(acc[mt][nt][3])
                        : "r"(a[mt][0]), "r"(a[mt][1]), "r"(a[mt][2]),
                          "r"(a[mt][3]), "r"(b[nt][0]), "r"(b[nt][1]));
        }
    };

    const int NIT = KDIM / 32;   // 16
    issue(0, 0);
    for (int it = 0; it < NIT; it++) {
        if (it + 1 < NIT) {
            issue((it + 1) & 1, (it + 1) * 32);
            asm volatile("cp.async.wait_group 1;");
        } else {
            asm volatile("cp.async.wait_group 0;");
        }
        __syncthreads();
        compute(it & 1);
        __syncthreads();
    }

    // epilogue: + bias
#pragma unroll
    for (int mt = 0; mt < 4; mt++) {
        int r0 = bm + wm + mt * 16 + g;
#pragma unroll
        for (int nt = 0; nt < 4; nt++) {
            int c = bn + wn + nt * 8 + tg * 2;
            float b0 = bias[c], b1 = bias[c + 1];
            float2 v0 = make_float2(acc[mt][nt][0] + b0, acc[mt][nt][1] + b1);
            float2 v1 = make_float2(acc[mt][nt][2] + b0, acc[mt][nt][3] + b1);
            *reinterpret_cast<float2*>(&C[(size_t)r0 * Nt + c]) = v0;
            *reinterpret_cast<float2*>(&C[(size_t)(r0 + 8) * Nt + c]) = v1;
        }
    }
}

// ---------------------------------------------------------------------------
// Banded window attention. One block per (b,i), one thread per head.
// Output tf32-rounded (it feeds the Wo GEMM).
// ---------------------------------------------------------------------------
__global__ void attn_kernel(const float* __restrict__ QKV,
                            float* __restrict__ out, int is_right) {
    const int bi = blockIdx.x;
    const int b = bi / NN;
    const int i = bi % NN;
    const int h = threadIdx.x;

    const float4* qv = reinterpret_cast<const float4*>(QKV + (size_t)bi * 1536 + h * 8);
    const float4 q0 = qv[0], q1 = qv[1];

    const int j0 = is_right ? i : (i - WID - 1);

    float sc[WINSZ];
    float mx = -1e30f;
#pragma unroll
    for (int t = 0; t < WINSZ; t++) {
        int j = j0 + t;
        bool valid = (j >= 0) && (j < NN);
        int jc = min(max(j, 0), NN - 1);
        const float4* kv = reinterpret_cast<const float4*>(
            QKV + ((size_t)(b * NN + jc)) * 1536 + 512 + h * 8);
        float4 k0 = kv[0], k1 = kv[1];
        float s = q0.x * k0.x + q0.y * k0.y + q0.z * k0.z + q0.w * k0.w +
                  q1.x * k1.x + q1.y * k1.y + q1.z * k1.z + q1.w * k1.w;
        s *= 0.35355339059327373f;
        sc[t] = valid ? s : -1e30f;
        mx = fmaxf(mx, sc[t]);
    }
    float sum = 0.0f;
#pragma unroll
    for (int t = 0; t < WINSZ; t++) {
        sc[t] = expf(sc[t] - mx);
        sum += sc[t];
    }
    const float inv = 1.0f / sum;

    float4 a0 = make_float4(0.f, 0.f, 0.f, 0.f);
    float4 a1 = make_float4(0.f, 0.f, 0.f, 0.f);
#pragma unroll
    for (int t = 0; t < WINSZ; t++) {
        int j = j0 + t;
        int jc = min(max(j, 0), NN - 1);
        const float4* vv = reinterpret_cast<const float4*>(
            QKV + ((size_t)(b * NN + jc)) * 1536 + 1024 + h * 8);
        float4 v0 = vv[0], v1 = vv[1];
        float p = sc[t] * inv;
        a0.x += p * v0.x; a0.y += p * v0.y; a0.z += p * v0.z; a0.w += p * v0.w;
        a1.x += p * v1.x; a1.y += p * v1.y; a1.z += p * v1.z; a1.w += p * v1.w;
    }
    float4* op = reinterpret_cast<float4*>(out + (size_t)bi * DD + h * 8);
    op[0] = rtf32_4(a0);
    op[1] = rtf32_4(a1);
}

// ---------------------------------------------------------------------------
// Slice rows [WIDTH : WIDTH+S] -> [B*S, D], tf32-rounded (feeds highway GEMM)
// ---------------------------------------------------------------------------
__global__ void copy_slice_kernel(const float* __restrict__ src,
                                  float* __restrict__ dst) {
    int t = blockIdx.x * blockDim.x + threadIdx.x;
    const int TOT = MH * (DD / 4);
    if (t >= TOT) return;
    int r = t / (DD / 4);
    int c4 = t % (DD / 4);
    int b = r / SS;
    int s = r % SS;
    float4 v = reinterpret_cast<const float4*>(src)[((size_t)(b * NN + WID + s)) * (DD / 4) + c4];
    reinterpret_cast<float4*>(dst)[t] = rtf32_4(v);
}

// ---------------------------------------------------------------------------
// Highway elementwise. do_round=1 when output feeds another GEMM.
// ---------------------------------------------------------------------------
__global__ void highway_ew_kernel(float* __restrict__ x,
                                  const float* __restrict__ hp, int do_round) {
    int idx = blockIdx.x * blockDim.x + threadIdx.x;
    const int TOT = MH * DD;
    if (idx >= TOT) return;
    int r = idx / DD;
    int c = idx % DD;
    float p = hp[(size_t)r * (2 * DD) + c];
    float gt = hp[(size_t)r * (2 * DD) + DD + c];
    float nl = fmaxf(p, 0.0f);
    float gate = 1.0f / (1.0f + expf(-gt));
    float v = gate * x[idx] + (1.0f - gate) * nl;
    x[idx] = do_round ? rtf32(v) : v;
}

// ---------------------------------------------------------------------------
// Output: last = concat(left, right); tuple (last[None], last) = data twice
// ---------------------------------------------------------------------------
__global__ void write_out_kernel(const float* __restrict__ hl,
                                 const float* __restrict__ hr,
                                 float* __restrict__ out, int out_size) {
    int t = blockIdx.x * blockDim.x + threadIdx.x;
    const int TOT4 = MH * (2 * DD / 4);
    if (t >= TOT4) return;
    int r = t >> 8;
    int c4 = t & 255;
    float4 v = (c4 < 128)
        ? reinterpret_cast<const float4*>(hl)[r * 128 + c4]
        : reinterpret_cast<const float4*>(hr)[r * 128 + (c4 - 128)];
    reinterpret_cast<float4*>(out)[t] = v;
    long long second = (long long)(t + TOT4) * 4 + 3;
    if (second < (long long)out_size)
        reinterpret_cast<float4*>(out)[t + TOT4] = v;
}

// ---------------------------------------------------------------------------
// Launch
// ---------------------------------------------------------------------------
extern "C" void kernel_launch(void* const* d_in, const int* in_sizes, int n_in,
                              void* d_out, int out_size) {
    const float* inputs    = (const float*)d_in[0];
    const float* left_pad  = (const float*)d_in[1];
    const float* right_pad = (const float*)d_in[2];
    const float* l_Wqkv    = (const float*)d_in[3];
    const float* l_bqkv    = (const float*)d_in[4];
    const float* l_Wo      = (const float*)d_in[5];
    const float* l_bo      = (const float*)d_in[6];
    const float* r_Wqkv    = (const float*)d_in[7];
    const float* r_bqkv    = (const float*)d_in[8];
    const float* r_Wo      = (const float*)d_in[9];
    const float* r_bo      = (const float*)d_in[10];
    const float* lhw_W     = (const float*)d_in[11];
    const float* lhw_b     = (const float*)d_in[12];
    const float* rhw_W     = (const float*)d_in[13];
    const float* rhw_b     = (const float*)d_in[14];
    float* out = (float*)d_out;

    float *pX, *pQKV0, *pQKV1, *pATT0, *pATT1, *pPROJ0, *pPROJ1, *pHX0, *pHX1,
          *pHP, *pWC;
    cudaGetSymbolAddress((void**)&pX,    g_X);
    cudaGetSymbolAddress((void**)&pQKV0, g_QKV0);
    cudaGetSymbolAddress((void**)&pQKV1, g_QKV1);
    cudaGetSymbolAddress((void**)&pATT0, g_ATT0);
    cudaGetSymbolAddress((void**)&pATT1, g_ATT1);
    cudaGetSymbolAddress((void**)&pPROJ0, g_PROJ0);
    cudaGetSymbolAddress((void**)&pPROJ1, g_PROJ1);
    cudaGetSymbolAddress((void**)&pHX0,  g_HX0);
    cudaGetSymbolAddress((void**)&pHX1,  g_HX1);
    cudaGetSymbolAddress((void**)&pHP,   g_HP);
    cudaGetSymbolAddress((void**)&pWC,   g_WC);

    cudaFuncSetAttribute(gemm_tf32_kernel,
                         cudaFuncAttributeMaxDynamicSharedMemorySize, GEMM_SMEM);

    // 0) convert weights to tf32-rounded values
    convert_weights_kernel<<<(1048576 + 255) / 256, 256>>>(
        l_Wqkv, r_Wqkv, l_Wo, r_Wo, lhw_W, rhw_W, pWC);

    // 1) padded, rounded input
    {
        int tot = MQ * (DD / 4);
        pad_kernel<<<(tot + 255) / 256, 256>>>(inputs, left_pad, right_pad, pX);
    }

    const float* bqkv[2] = {l_bqkv, r_bqkv};
    const float* bo[2]   = {l_bo, r_bo};
    const float* hwB[2]  = {lhw_b, rhw_b};
    const float* Wqkv[2] = {pWC + 0,       pWC + 786432};
    const float* Wo[2]   = {pWC + 1572864, pWC + 1835008};
    const float* hwW[2]  = {pWC + 2097152, pWC + 3145728};
    float* QKV[2]  = {pQKV0, pQKV1};
    float* ATT[2]  = {pATT0, pATT1};
    float* PROJ[2] = {pPROJ0, pPROJ1};
    float* HX[2]   = {pHX0, pHX1};

    for (int side = 0; side < 2; side++) {
        // QKV projection: [4352,512] @ [1536,512]^T
        gemm_tf32_kernel<<<dim3((3 * DD) / 128, MQ / 128), 256, GEMM_SMEM>>>(
            pX, Wqkv[side], bqkv[side], QKV[side], 3 * DD);

        // windowed attention
        attn_kernel<<<MQ, HH>>>(QKV[side], ATT[side], side);

        // output projection
        gemm_tf32_kernel<<<dim3(DD / 128, MQ / 128), 256, GEMM_SMEM>>>(
            ATT[side], Wo[side], bo[side], PROJ[side], DD);

        // slice
        {
            int tot = MH * (DD / 4);
            copy_slice_kernel<<<(tot + 255) / 256, 256>>>(PROJ[side], HX[side]);
        }

        // highway layers
        for (int l = 0; l < 2; l++) {
            gemm_tf32_kernel<<<dim3((2 * DD) / 128, MH / 128), 256, GEMM_SMEM>>>(
                HX[side], hwW[side] + (size_t)l * (2 * DD) * DD,
                hwB[side] + (size_t)l * (2 * DD), pHP, 2 * DD);
            int tot = MH * DD;
            highway_ew_kernel<<<(tot + 255) / 256, 256>>>(HX[side], pHP,
                                                          l == 0 ? 1 : 0);
        }
    }

    // final concat + duplicate write
    {
        int tot4 = MH * (2 * DD / 4);
        write_out_kernel<<<(tot4 + 255) / 256, 256>>>(pHX0, pHX1, out, out_size);
    }
}

// round 5
// speedup vs baseline: 2.4282x; 1.0548x over previous
#include <cuda_runtime.h>
#include <cstdint>
#include <math.h>

// ---------------------------------------------------------------------------
// Problem constants
// ---------------------------------------------------------------------------
#define BB    8
#define SS    512
#define DD    512
#define HH    64
#define WID   16
#define NN    (SS + 2 * WID)      // 544
#define MQ    (BB * NN)           // 4352
#define MH    (BB * SS)           // 4096
#define KDIM  512
#define WINSZ (WID + 2)           // 18

// ---------------------------------------------------------------------------
// Scratch (static device memory; allocation is forbidden)
// ---------------------------------------------------------------------------
__device__ float g_X[MQ * DD];                  // padded input, tf32-rounded
__device__ float g_QKVcat[MQ * 3072];           // both sides' qkv [B*N, 3072]
__device__ float g_ATT0[MQ * DD];
__device__ float g_ATT1[MQ * DD];
__device__ float g_HX0[MH * DD];
__device__ float g_HX1[MH * DD];
__device__ float g_HY0[MH * DD];
__device__ float g_HY1[MH * DD];
// tf32-rounded weights, packed (floats):
//  [0]        l_Wqkv  1536*512
//  [786432]   r_Wqkv  1536*512
//  [1572864]  l_Wo     512*512
//  [1835008]  r_Wo     512*512
//  [2097152]  lhw_W   2*1024*512  (rows interleaved: 2c=proj_c, 2c+1=gate_c)
//  [3145728]  rhw_W   2*1024*512  (same interleave)
__device__ float g_WC[4194304];
// biases: [0..3071] qkv cat (l then r); [3072..7167] hw interleaved
//         (side*2048 + layer*1024 + j)
__device__ float g_B[7168];

// ---------------------------------------------------------------------------
// tf32 rounding helper
// ---------------------------------------------------------------------------
__device__ __forceinline__ float rtf32(float x) {
    uint32_t r;
    asm("cvt.rna.tf32.f32 %0, %1;" : "=r"(r) : "f"(x));
    return __uint_as_float(r);
}
__device__ __forceinline__ float4 rtf32_4(float4 v) {
    v.x = rtf32(v.x); v.y = rtf32(v.y); v.z = rtf32(v.z); v.w = rtf32(v.w);
    return v;
}

// ---------------------------------------------------------------------------
// Convert weights to tf32-rounded fp32, packed into g_WC.
// Sections (float4 units): [0,196608) l_qkv, [196608,393216) r_qkv,
// [393216,458752) l_wo, [458752,524288) r_wo, [524288,1048576) hw (row-perm).
// ---------------------------------------------------------------------------
__global__ void convert_weights_kernel(const float* __restrict__ lqkv,
                                       const float* __restrict__ rqkv,
                                       const float* __restrict__ lwo,
                                       const float* __restrict__ rwo,
                                       const float* __restrict__ lhw,
                                       const float* __restrict__ rhw,
                                       float* __restrict__ out) {
    int t = blockIdx.x * blockDim.x + threadIdx.x;
    if (t >= 1048576) return;
    const float* src;
    int loc;
    if (t < 196608)      { src = lqkv; loc = t; }
    else if (t < 393216) { src = rqkv; loc = t - 196608; }
    else if (t < 458752) { src = lwo;  loc = t - 393216; }
    else if (t < 524288) { src = rwo;  loc = t - 458752; }
    else {
        int u = t - 524288;
        int side  = u / 262144;
        int v     = u % 262144;
        int layer = v / 131072;
        int w     = v % 131072;
        int j     = w / 128;           // dest row (interleaved)
        int c4    = w % 128;
        int srow  = (j & 1) ? (512 + (j >> 1)) : (j >> 1);
        src = side ? rhw : lhw;
        loc = layer * 131072 + srow * 128 + c4;
    }
    float4 v = reinterpret_cast<const float4*>(src)[loc];
    reinterpret_cast<float4*>(out)[t] = rtf32_4(v);
}

// biases: qkv concat + highway interleave-permuted
__global__ void bias_cat_kernel(const float* __restrict__ lbq,
                                const float* __restrict__ rbq,
                                const float* __restrict__ lhb,
                                const float* __restrict__ rhb,
                                float* __restrict__ B) {
    int t = blockIdx.x * blockDim.x + threadIdx.x;
    if (t >= 7168) return;
    if (t < 1536)       B[t] = lbq[t];
    else if (t < 3072)  B[t] = rbq[t - 1536];
    else {
        int u = t - 3072;
        int side  = u >> 11;
        int layer = (u >> 10) & 1;
        int j     = u & 1023;
        int c     = j >> 1;
        int srcj  = (j & 1) ? (512 + c) : c;
        const float* hb = side ? rhb : lhb;
        B[t] = hb[layer * 1024 + srcj];
    }
}

// ---------------------------------------------------------------------------
// Padded input (tf32-rounded)
// ---------------------------------------------------------------------------
__global__ void pad_kernel(const float* __restrict__ inp,
                           const float* __restrict__ lp,
                           const float* __restrict__ rp,
                           float* __restrict__ X) {
    int t = blockIdx.x * blockDim.x + threadIdx.x;
    const int TOT = MQ * (DD / 4);
    if (t >= TOT) return;
    int row = t / (DD / 4);
    int c4  = t % (DD / 4);
    int b = row / NN;
    int n = row % NN;
    float4 v;
    if (n < WID) {
        v = reinterpret_cast<const float4*>(lp)[n * (DD / 4) + c4];
    } else if (n >= WID + SS) {
        v = reinterpret_cast<const float4*>(rp)[(n - WID - SS) * (DD / 4) + c4];
    } else {
        v = reinterpret_cast<const float4*>(inp)[((size_t)b * SS + (n - WID)) * (DD / 4) + c4];
    }
    reinterpret_cast<float4*>(X)[t] = rtf32_4(v);
}

// ---------------------------------------------------------------------------
// TF32 tensor-core GEMM with fused epilogues.
//   mode 0: C = A@W^T + bias          (plain, stride Nt)
//   mode 1: Wo + row-slice [WID:WID+SS] -> C (stride 512), tf32-rounded
//   mode 2: highway layer, C = gate*A + (1-gate)*relu(proj), tf32-rounded
//   mode 3: highway layer, same, no rounding
// blockIdx.z selects the (A,W,bias,C) set (two sides).
// ---------------------------------------------------------------------------
#define STRIDE      36
#define TILE_WORDS  (128 * STRIDE)        // 4608
#define STAGE_WORDS (2 * TILE_WORDS)      // 9216
#define GEMM_SMEM   (2 * STAGE_WORDS * 4) // 73728 bytes

__global__ __launch_bounds__(256) void gemm_fused_kernel(
    const float* __restrict__ A0, const float* __restrict__ A1,
    const float* __restrict__ W0, const float* __restrict__ W1,
    const float* __restrict__ B0, const float* __restrict__ B1,
    float* __restrict__ C0, float* __restrict__ C1,
    int Nt, int mode) {
    extern __shared__ uint32_t sm[];

    const int z = blockIdx.z;
    const float* A = z ? A1 : A0;
    const float* W = z ? W1 : W0;
    const float* bias = z ? B1 : B0;
    float* C = z ? C1 : C0;

    const int bm = blockIdx.y * 128;
    const int bn = blockIdx.x * 128;
    const int tid = threadIdx.x;
    const int lane = tid & 31;
    const int wrp = tid >> 5;
    const int wm = (wrp & 1) * 64;
    const int wn = (wrp >> 1) * 32;
    const int g  = lane >> 2;
    const int tg = lane & 3;

    const int lrow = tid >> 1;
    const int half = tid & 1;
    const float* Abase = A + (size_t)(bm + lrow) * KDIM + half * 16;
    const float* Wbase = W + (size_t)(bn + lrow) * KDIM + half * 16;
    const uint32_t dstA =
        (uint32_t)__cvta_generic_to_shared(&sm[lrow * STRIDE + half * 16]);

    float acc[4][4][4];
#pragma unroll
    for (int mt = 0; mt < 4; mt++)
#pragma unroll
        for (int nt = 0; nt < 4; nt++)
#pragma unroll
            for (int r = 0; r < 4; r++) acc[mt][nt][r] = 0.0f;

    auto issue = [&](int s, int k0) {
        uint32_t da = dstA + s * STAGE_WORDS * 4;
        uint32_t dw = da + TILE_WORDS * 4;
        const float* sa = Abase + k0;
        const float* sw = Wbase + k0;
#pragma unroll
        for (int i = 0; i < 4; i++) {
            asm volatile("cp.async.cg.shared.global [%0], [%1], 16;"
                         :: "r"(da + i * 16), "l"(sa + i * 4));
            asm volatile("cp.async.cg.shared.global [%0], [%1], 16;"
                         :: "r"(dw + i * 16), "l"(sw + i * 4));
        }
        asm volatile("cp.async.commit_group;");
    };

    auto compute = [&](int s) {
        const uint32_t* As = sm + s * STAGE_WORDS;
        const uint32_t* Ws = As + TILE_WORDS;
#pragma unroll
        for (int kk = 0; kk < 4; kk++) {
            uint32_t a[4][4], b[4][2];
#pragma unroll
            for (int mt = 0; mt < 4; mt++) {
                int rb = wm + mt * 16;
                a[mt][0] = As[(rb + g) * STRIDE + kk * 8 + tg];
                a[mt][1] = As[(rb + g + 8) * STRIDE + kk * 8 + tg];
                a[mt][2] = As[(rb + g) * STRIDE + kk * 8 + tg + 4];
                a[mt][3] = As[(rb + g + 8) * STRIDE + kk * 8 + tg + 4];
            }
#pragma unroll
            for (int nt = 0; nt < 4; nt++) {
                int cb = wn + nt * 8;
                b[nt][0] = Ws[(cb + g) * STRIDE + kk * 8 + tg];
                b[nt][1] = Ws[(cb + g) * STRIDE + kk * 8 + tg + 4];
            }
#pragma unroll
            for (int mt = 0; mt < 4; mt++)
#pragma unroll
                for (int nt = 0; nt < 4; nt++)
                    asm volatile(
                        "mma.sync.aligned.m16n8k8.row.col.f32.tf32.tf32.f32 "
                        "{%0,%1,%2,%3},{%4,%5,%6,%7},{%8,%9},{%0,%1,%2,%3};"
                        : "+f"(acc[mt][nt][0]), "+f"(acc[mt][nt][1]),
                          "+f"(acc[mt][nt][2]), "+f"(acc[mt][nt][3])
                        : "r"(a[mt][0]), "r"(a[mt][1]), "r"(a[mt][2]),
                          "r"(a[mt][3]), "r"(b[nt][0]), "r"(b[nt][1]));
        }
    };

    const int NIT = KDIM / 32;
    issue(0, 0);
    for (int it = 0; it < NIT; it++) {
        if (it + 1 < NIT) {
            issue((it + 1) & 1, (it + 1) * 32);
            asm volatile("cp.async.wait_group 1;");
        } else {
            asm volatile("cp.async.wait_group 0;");
        }
        __syncthreads();
        compute(it & 1);
        __syncthreads();
    }

    // ---------------- epilogues ----------------
    if (mode == 0) {
#pragma unroll
        for (int mt = 0; mt < 4; mt++) {
            int r0 = bm + wm + mt * 16 + g;
#pragma unroll
            for (int nt = 0; nt < 4; nt++) {
                int c = bn + wn + nt * 8 + tg * 2;
                float b0 = bias[c], b1 = bias[c + 1];
                float2 v0 = make_float2(acc[mt][nt][0] + b0, acc[mt][nt][1] + b1);
                float2 v1 = make_float2(acc[mt][nt][2] + b0, acc[mt][nt][3] + b1);
                *reinterpret_cast<float2*>(&C[(size_t)r0 * Nt + c]) = v0;
                *reinterpret_cast<float2*>(&C[(size_t)(r0 + 8) * Nt + c]) = v1;
            }
        }
    } else if (mode == 1) {
        // Wo + slice: row r -> (b, n); keep n in [WID, WID+SS); C stride 512
#pragma unroll
        for (int mt = 0; mt < 4; mt++) {
            int r0 = bm + wm + mt * 16 + g;
#pragma unroll
            for (int half_r = 0; half_r < 2; half_r++) {
                int r = r0 + half_r * 8;
                int b = r / NN;
                int n = r % NN;
                if (n < WID || n >= WID + SS) continue;
                int drow = b * SS + (n - WID);
#pragma unroll
                for (int nt = 0; nt < 4; nt++) {
                    int c = bn + wn + nt * 8 + tg * 2;
                    float b0 = bias[c], b1 = bias[c + 1];
                    float2 v;
                    v.x = rtf32(acc[mt][nt][0 + 2 * half_r] + b0);
                    v.y = rtf32(acc[mt][nt][1 + 2 * half_r] + b1);
                    *reinterpret_cast<float2*>(&C[(size_t)drow * DD + c]) = v;
                }
            }
        }
    } else {
        // highway: acc pair = (proj, gate) for channel col/2; x_old = A
#pragma unroll
        for (int mt = 0; mt < 4; mt++) {
            int r0 = bm + wm + mt * 16 + g;
#pragma unroll
            for (int nt = 0; nt < 4; nt++) {
                int col = bn + wn + nt * 8 + tg * 2;
                int ch = col >> 1;
                float b0 = bias[col], b1 = bias[col + 1];
#pragma unroll
                for (int half_r = 0; half_r < 2; half_r++) {
                    int r = r0 + half_r * 8;
                    float p  = acc[mt][nt][0 + 2 * half_r] + b0;
                    float gt = acc[mt][nt][1 + 2 * half_r] + b1;
                    float xo = A[(size_t)r * DD + ch];
                    float gate = 1.0f / (1.0f + expf(-gt));
                    float v = gate * xo + (1.0f - gate) * fmaxf(p, 0.0f);
                    C[(size_t)r * DD + ch] = (mode == 2) ? rtf32(v) : v;
                }
            }
        }
    }
}

// ---------------------------------------------------------------------------
// Banded window attention, both sides in one launch.
// 256 threads = 4 tuples x 64 heads. QKVcat row stride 3072.
// ---------------------------------------------------------------------------
__global__ void attn_kernel(const float* __restrict__ QKV,
                            float* __restrict__ out0,
                            float* __restrict__ out1) {
    const int t = blockIdx.x * 4 + (threadIdx.x >> 6);
    const int h = threadIdx.x & 63;
    const int side = (t >= MQ) ? 1 : 0;
    const int bi = t - side * MQ;
    const int b = bi / NN;
    const int i = bi % NN;
    const int soff = side * 1536;

    const float4* qv = reinterpret_cast<const float4*>(
        QKV + (size_t)bi * 3072 + soff + h * 8);
    const float4 q0 = qv[0], q1 = qv[1];

    const int j0 = side ? i : (i - WID - 1);

    float sc[WINSZ];
    float mx = -1e30f;
#pragma unroll
    for (int tt = 0; tt < WINSZ; tt++) {
        int j = j0 + tt;
        bool valid = (j >= 0) && (j < NN);
        int jc = min(max(j, 0), NN - 1);
        const float4* kv = reinterpret_cast<const float4*>(
            QKV + ((size_t)(b * NN + jc)) * 3072 + soff + 512 + h * 8);
        float4 k0 = kv[0], k1 = kv[1];
        float s = q0.x * k0.x + q0.y * k0.y + q0.z * k0.z + q0.w * k0.w +
                  q1.x * k1.x + q1.y * k1.y + q1.z * k1.z + q1.w * k1.w;
        s *= 0.35355339059327373f;
        sc[tt] = valid ? s : -1e30f;
        mx = fmaxf(mx, sc[tt]);
    }
    float sum = 0.0f;
#pragma unroll
    for (int tt = 0; tt < WINSZ; tt++) {
        sc[tt] = expf(sc[tt] - mx);
        sum += sc[tt];
    }
    const float inv = 1.0f / sum;

    float4 a0 = make_float4(0.f, 0.f, 0.f, 0.f);
    float4 a1 = make_float4(0.f, 0.f, 0.f, 0.f);
#pragma unroll
    for (int tt = 0; tt < WINSZ; tt++) {
        int j = j0 + tt;
        int jc = min(max(j, 0), NN - 1);
        const float4* vv = reinterpret_cast<const float4*>(
            QKV + ((size_t)(b * NN + jc)) * 3072 + soff + 1024 + h * 8);
        float4 v0 = vv[0], v1 = vv[1];
        float p = sc[tt] * inv;
        a0.x += p * v0.x; a0.y += p * v0.y; a0.z += p * v0.z; a0.w += p * v0.w;
        a1.x += p * v1.x; a1.y += p * v1.y; a1.z += p * v1.z; a1.w += p * v1.w;
    }
    float* out = side ? out1 : out0;
    float4* op = reinterpret_cast<float4*>(out + (size_t)bi * DD + h * 8);
    op[0] = rtf32_4(a0);
    op[1] = rtf32_4(a1);
}

// ---------------------------------------------------------------------------
// Output: last = concat(left, right); tuple (last[None], last) = data twice
// ---------------------------------------------------------------------------
__global__ void write_out_kernel(const float* __restrict__ hl,
                                 const float* __restrict__ hr,
                                 float* __restrict__ out, int out_size) {
    int t = blockIdx.x * blockDim.x + threadIdx.x;
    const int TOT4 = MH * (2 * DD / 4);
    if (t >= TOT4) return;
    int r = t >> 8;
    int c4 = t & 255;
    float4 v = (c4 < 128)
        ? reinterpret_cast<const float4*>(hl)[r * 128 + c4]
        : reinterpret_cast<const float4*>(hr)[r * 128 + (c4 - 128)];
    reinterpret_cast<float4*>(out)[t] = v;
    long long second = (long long)(t + TOT4) * 4 + 3;
    if (second < (long long)out_size)
        reinterpret_cast<float4*>(out)[t + TOT4] = v;
}

// ---------------------------------------------------------------------------
// Launch
// ---------------------------------------------------------------------------
extern "C" void kernel_launch(void* const* d_in, const int* in_sizes, int n_in,
                              void* d_out, int out_size) {
    const float* inputs    = (const float*)d_in[0];
    const float* left_pad  = (const float*)d_in[1];
    const float* right_pad = (const float*)d_in[2];
    const float* l_Wqkv    = (const float*)d_in[3];
    const float* l_bqkv    = (const float*)d_in[4];
    const float* l_Wo      = (const float*)d_in[5];
    const float* l_bo      = (const float*)d_in[6];
    const float* r_Wqkv    = (const float*)d_in[7];
    const float* r_bqkv    = (const float*)d_in[8];
    const float* r_Wo      = (const float*)d_in[9];
    const float* r_bo      = (const float*)d_in[10];
    const float* lhw_W     = (const float*)d_in[11];
    const float* lhw_b     = (const float*)d_in[12];
    const float* rhw_W     = (const float*)d_in[13];
    const float* rhw_b     = (const float*)d_in[14];
    float* out = (float*)d_out;

    float *pX, *pQKV, *pATT0, *pATT1, *pHX0, *pHX1, *pHY0, *pHY1, *pWC, *pB;
    cudaGetSymbolAddress((void**)&pX,    g_X);
    cudaGetSymbolAddress((void**)&pQKV,  g_QKVcat);
    cudaGetSymbolAddress((void**)&pATT0, g_ATT0);
    cudaGetSymbolAddress((void**)&pATT1, g_ATT1);
    cudaGetSymbolAddress((void**)&pHX0,  g_HX0);
    cudaGetSymbolAddress((void**)&pHX1,  g_HX1);
    cudaGetSymbolAddress((void**)&pHY0,  g_HY0);
    cudaGetSymbolAddress((void**)&pHY1,  g_HY1);
    cudaGetSymbolAddress((void**)&pWC,   g_WC);
    cudaGetSymbolAddress((void**)&pB,    g_B);

    cudaFuncSetAttribute(gemm_fused_kernel,
                         cudaFuncAttributeMaxDynamicSharedMemorySize, GEMM_SMEM);

    // 0) weights + biases (tf32 / permuted)
    convert_weights_kernel<<<(1048576 + 255) / 256, 256>>>(
        l_Wqkv, r_Wqkv, l_Wo, r_Wo, lhw_W, rhw_W, pWC);
    bias_cat_kernel<<<(7168 + 255) / 256, 256>>>(l_bqkv, r_bqkv, lhw_b, rhw_b, pB);

    // 1) padded, rounded input
    pad_kernel<<<(MQ * (DD / 4) + 255) / 256, 256>>>(inputs, left_pad, right_pad, pX);

    // 2) merged QKV GEMM: [4352,512] @ [3072,512]^T  (both sides)
    gemm_fused_kernel<<<dim3(3072 / 128, MQ / 128, 1), 256, GEMM_SMEM>>>(
        pX, pX, pWC, pWC, pB, pB, pQKV, pQKV, 3072, 0);

    // 3) windowed attention, both sides
    attn_kernel<<<(2 * MQ) / 4, 256>>>(pQKV, pATT0, pATT1);

    // 4) Wo GEMM + slice, both sides via z
    gemm_fused_kernel<<<dim3(DD / 128, MQ / 128, 2), 256, GEMM_SMEM>>>(
        pATT0, pATT1, pWC + 1572864, pWC + 1835008, l_bo, r_bo,
        pHX0, pHX1, DD, 1);

    // 5) highway layer 0: HX -> HY (rounded), both sides
    gemm_fused_kernel<<<dim3(1024 / 128, MH / 128, 2), 256, GEMM_SMEM>>>(
        pHX0, pHX1, pWC + 2097152, pWC + 3145728,
        pB + 3072, pB + 3072 + 2048, pHY0, pHY1, 1024, 2);

    // 6) highway layer 1: HY -> HX (unrounded), both sides
    gemm_fused_kernel<<<dim3(1024 / 128, MH / 128, 2), 256, GEMM_SMEM>>>(
        pHY0, pHY1, pWC + 2097152 + 524288, pWC + 3145728 + 524288,
        pB + 3072 + 1024, pB + 3072 + 2048 + 1024, pHX0, pHX1, 1024, 3);

    // 7) final concat + duplicate write
    write_out_kernel<<<(MH * (2 * DD / 4) + 255) / 256, 256>>>(
        pHX0, pHX1, out, out_size);
}

// round 7
// speedup vs baseline: 3.4380x; 1.4159x over previous
#include <cuda_runtime.h>
#include <cstdint>
#include <math.h>

// ---------------------------------------------------------------------------
// Problem constants
// ---------------------------------------------------------------------------
#define BB    8
#define SS    512
#define DD    512
#define HH    64
#define WID   16
#define NN    (SS + 2 * WID)      // 544
#define MQ    (BB * NN)           // 4352
#define MH    (BB * SS)           // 4096
#define KDIM  512
#define WINSZ (WID + 2)           // 18

// GEMM tiling: 128x128 tile, BK=32, 3-stage cp.async ring
#define RSTR     36                         // smem row stride in words (pad)
#define A_BYTES  (128 * RSTR * 4)           // 18432
#define STG_BYTES (2 * A_BYTES)             // 36864 (A tile + W tile)
#define NSTG     3
#define DYN_SMEM (NSTG * STG_BYTES)         // 110592

// ---------------------------------------------------------------------------
// Scratch (static device memory; allocation is forbidden)
// ---------------------------------------------------------------------------
__device__ float g_X[MQ * DD];
__device__ float g_QKVcat[MQ * 3072];
__device__ float g_ATT0[MQ * DD];
__device__ float g_ATT1[MQ * DD];
__device__ float g_HX0[MH * DD];
__device__ float g_HX1[MH * DD];
__device__ float g_HY0[MH * DD];
__device__ float g_HY1[MH * DD];
// tf32-rounded weights, packed (floats): see convert_weights_kernel
__device__ float g_WC[4194304];
// biases: [0..3071] qkv cat (l then r); [3072..7167] hw interleaved
__device__ float g_B[7168];

// ---------------------------------------------------------------------------
// helpers
// ---------------------------------------------------------------------------
__device__ __forceinline__ float rtf32(float x) {
    uint32_t r;
    asm("cvt.rna.tf32.f32 %0, %1;" : "=r"(r) : "f"(x));
    return __uint_as_float(r);
}
__device__ __forceinline__ float4 rtf32_4(float4 v) {
    v.x = rtf32(v.x); v.y = rtf32(v.y); v.z = rtf32(v.z); v.w = rtf32(v.w);
    return v;
}

// ---------------------------------------------------------------------------
// Convert weights to tf32-rounded fp32, packed into g_WC.
// ---------------------------------------------------------------------------
__global__ void convert_weights_kernel(const float* __restrict__ lqkv,
                                       const float* __restrict__ rqkv,
                                       const float* __restrict__ lwo,
                                       const float* __restrict__ rwo,
                                       const float* __restrict__ lhw,
                                       const float* __restrict__ rhw,
                                       float* __restrict__ out) {
    int t = blockIdx.x * blockDim.x + threadIdx.x;
    if (t >= 1048576) return;
    const float* src;
    int loc;
    if (t < 196608)      { src = lqkv; loc = t; }
    else if (t < 393216) { src = rqkv; loc = t - 196608; }
    else if (t < 458752) { src = lwo;  loc = t - 393216; }
    else if (t < 524288) { src = rwo;  loc = t - 458752; }
    else {
        int u = t - 524288;
        int side  = u / 262144;
        int v     = u % 262144;
        int layer = v / 131072;
        int w     = v % 131072;
        int j     = w / 128;           // dest row (interleaved proj/gate)
        int c4    = w % 128;
        int srow  = (j & 1) ? (512 + (j >> 1)) : (j >> 1);
        src = side ? rhw : lhw;
        loc = layer * 131072 + srow * 128 + c4;
    }
    float4 v = reinterpret_cast<const float4*>(src)[loc];
    reinterpret_cast<float4*>(out)[t] = rtf32_4(v);
}

__global__ void bias_cat_kernel(const float* __restrict__ lbq,
                                const float* __restrict__ rbq,
                                const float* __restrict__ lhb,
                                const float* __restrict__ rhb,
                                float* __restrict__ B) {
    int t = blockIdx.x * blockDim.x + threadIdx.x;
    if (t >= 7168) return;
    if (t < 1536)       B[t] = lbq[t];
    else if (t < 3072)  B[t] = rbq[t - 1536];
    else {
        int u = t - 3072;
        int side  = u >> 11;
        int layer = (u >> 10) & 1;
        int j     = u & 1023;
        int c     = j >> 1;
        int srcj  = (j & 1) ? (512 + c) : c;
        const float* hb = side ? rhb : lhb;
        B[t] = hb[layer * 1024 + srcj];
    }
}

// ---------------------------------------------------------------------------
// Padded input (tf32-rounded)
// ---------------------------------------------------------------------------
__global__ void pad_kernel(const float* __restrict__ inp,
                           const float* __restrict__ lp,
                           const float* __restrict__ rp,
                           float* __restrict__ X) {
    int t = blockIdx.x * blockDim.x + threadIdx.x;
    const int TOT = MQ * (DD / 4);
    if (t >= TOT) return;
    int row = t / (DD / 4);
    int c4  = t % (DD / 4);
    int b = row / NN;
    int n = row % NN;
    float4 v;
    if (n < WID) {
        v = reinterpret_cast<const float4*>(lp)[n * (DD / 4) + c4];
    } else if (n >= WID + SS) {
        v = reinterpret_cast<const float4*>(rp)[(n - WID - SS) * (DD / 4) + c4];
    } else {
        v = reinterpret_cast<const float4*>(inp)[((size_t)b * SS + (n - WID)) * (DD / 4) + c4];
    }
    reinterpret_cast<float4*>(X)[t] = rtf32_4(v);
}

// ---------------------------------------------------------------------------
// TF32 mma.sync GEMM: C[M, Nt] = A[M,512] @ W[Nt,512]^T, fused epilogues.
// 128x128 tile, BK=32, 8 warps (64x32 each), ldmatrix fragment loads,
// 3-stage cp.async ring with ONE __syncthreads per K-step.
//   mode 0: C = acc + bias                      (stride Nt)
//   mode 1: Wo + row-slice [WID,WID+SS) -> C (stride 512), tf32-rounded
//   mode 2: highway (interleaved proj/gate cols), rounded
//   mode 3: highway, unrounded
// blockIdx.z selects side.
// ---------------------------------------------------------------------------
__global__ __launch_bounds__(256, 2) void gemm_fused_kernel(
    const float* __restrict__ A0, const float* __restrict__ A1,
    const float* __restrict__ W0, const float* __restrict__ W1,
    const float* __restrict__ B0, const float* __restrict__ B1,
    float* __restrict__ C0, float* __restrict__ C1,
    int Nt, int mode) {
    extern __shared__ char dsm[];

    const int z = blockIdx.z;
    const float* A = z ? A1 : A0;
    const float* W = z ? W1 : W0;
    const float* bias = z ? B1 : B0;
    float* C = z ? C1 : C0;

    const int bm = blockIdx.y * 128;
    const int bn = blockIdx.x * 128;
    const int tid = threadIdx.x;
    const int lane = tid & 31;
    const int wrp = tid >> 5;
    const int wm = (wrp & 1) * 64;     // warp m offset
    const int wn = (wrp >> 1) * 32;    // warp n offset
    const int g  = lane >> 2;          // for epilogue / mma row
    const int tg = lane & 3;

    const uint32_t smemBase = (uint32_t)__cvta_generic_to_shared(dsm);

    // ldmatrix per-lane provider offsets (bytes)
    const uint32_t aOff =
        ((wm + ((lane >> 3) & 1) * 8 + (lane & 7)) * RSTR + (lane >> 4) * 4) * 4;
    const uint32_t bOff =
        ((wn + ((lane >> 4) & 1) * 8 + (lane & 7)) * RSTR + ((lane >> 3) & 1) * 4) * 4;

    // global->smem: each thread copies 4 float4 of A and 4 of W per stage
    const int lr = tid >> 3;           // row group base (tid/8), +32 per i
    const int lc = tid & 7;            // 16B chunk within row

    float acc[4][4][4];
#pragma unroll
    for (int mt = 0; mt < 4; mt++)
#pragma unroll
        for (int nt = 0; nt < 4; nt++)
#pragma unroll
            for (int r = 0; r < 4; r++) acc[mt][nt][r] = 0.0f;

    auto issue = [&](int s, int k0) {
        uint32_t base = smemBase + s * STG_BYTES;
#pragma unroll
        for (int i = 0; i < 4; i++) {
            int r = lr + i * 32;
            uint32_t dst = base + (r * RSTR + lc * 4) * 4;
            const float* src = A + (size_t)(bm + r) * KDIM + k0 + lc * 4;
            asm volatile("cp.async.cg.shared.global [%0], [%1], 16;"
                         :: "r"(dst), "l"(src));
        }
#pragma unroll
        for (int i = 0; i < 4; i++) {
            int r = lr + i * 32;
            uint32_t dst = base + A_BYTES + (r * RSTR + lc * 4) * 4;
            const float* src = W + (size_t)(bn + r) * KDIM + k0 + lc * 4;
            asm volatile("cp.async.cg.shared.global [%0], [%1], 16;"
                         :: "r"(dst), "l"(src));
        }
        asm volatile("cp.async.commit_group;");
    };

    auto compute = [&](int s) {
        const uint32_t aPtr = smemBase + s * STG_BYTES + aOff;
        const uint32_t wPtr = smemBase + s * STG_BYTES + A_BYTES + bOff;
#pragma unroll
        for (int kk = 0; kk < 4; kk++) {
            uint32_t a[4][4], b[4][2];
#pragma unroll
            for (int mt = 0; mt < 4; mt++) {
                uint32_t addr = aPtr + mt * (16 * RSTR * 4) + kk * 32;
                asm volatile(
                    "ldmatrix.sync.aligned.m8n8.x4.shared.b16 {%0,%1,%2,%3}, [%4];"
                    : "=r"(a[mt][0]), "=r"(a[mt][1]), "=r"(a[mt][2]),
                      "=r"(a[mt][3])
                    : "r"(addr));
            }
#pragma unroll
            for (int ntp = 0; ntp < 2; ntp++) {
                uint32_t addr = wPtr + ntp * (16 * RSTR * 4) + kk * 32;
                asm volatile(
                    "ldmatrix.sync.aligned.m8n8.x4.shared.b16 {%0,%1,%2,%3}, [%4];"
                    : "=r"(b[2 * ntp][0]), "=r"(b[2 * ntp][1]),
                      "=r"(b[2 * ntp + 1][0]), "=r"(b[2 * ntp + 1][1])
                    : "r"(addr));
            }
#pragma unroll
            for (int mt = 0; mt < 4; mt++)
#pragma unroll
                for (int nt = 0; nt < 4; nt++)
                    asm volatile(
                        "mma.sync.aligned.m16n8k8.row.col.f32.tf32.tf32.f32 "
                        "{%0,%1,%2,%3},{%4,%5,%6,%7},{%8,%9},{%0,%1,%2,%3};"
                        : "+f"(acc[mt][nt][0]), "+f"(acc[mt][nt][1]),
                          "+f"(acc[mt][nt][2]), "+f"(acc[mt][nt][3])
                        : "r"(a[mt][0]), "r"(a[mt][1]), "r"(a[mt][2]),
                          "r"(a[mt][3]), "r"(b[nt][0]), "r"(b[nt][1]));
        }
    };

    const int NIT = KDIM / 32;   // 16
    issue(0, 0);
    issue(1, 32);
    for (int it = 0; it < NIT; it++) {
        if (it < NIT - 2)
            asm volatile("cp.async.wait_group 1;");
        else
            asm volatile("cp.async.wait_group 0;");
        __syncthreads();
        if (it + 2 < NIT) issue((it + 2) % NSTG, (it + 2) * 32);
        compute(it % NSTG);
    }

    // ---------------- epilogues ----------------
    if (mode == 0) {
#pragma unroll
        for (int mt = 0; mt < 4; mt++) {
            int r0 = bm + wm + mt * 16 + g;
#pragma unroll
            for (int nt = 0; nt < 4; nt++) {
                int c = bn + wn + nt * 8 + tg * 2;
                float b0 = bias[c], b1 = bias[c + 1];
                float2 v0 = make_float2(acc[mt][nt][0] + b0, acc[mt][nt][1] + b1);
                float2 v1 = make_float2(acc[mt][nt][2] + b0, acc[mt][nt][3] + b1);
                *reinterpret_cast<float2*>(&C[(size_t)r0 * Nt + c]) = v0;
                *reinterpret_cast<float2*>(&C[(size_t)(r0 + 8) * Nt + c]) = v1;
            }
        }
    } else if (mode == 1) {
        // Wo + slice: row r -> (b, n); keep n in [WID, WID+SS); C stride 512
#pragma unroll
        for (int mt = 0; mt < 4; mt++) {
            int r0 = bm + wm + mt * 16 + g;
#pragma unroll
            for (int half_r = 0; half_r < 2; half_r++) {
                int r = r0 + half_r * 8;
                int b = r / NN;
                int n = r % NN;
                if (n < WID || n >= WID + SS) continue;
                int drow = b * SS + (n - WID);
#pragma unroll
                for (int nt = 0; nt < 4; nt++) {
                    int c = bn + wn + nt * 8 + tg * 2;
                    float b0 = bias[c], b1 = bias[c + 1];
                    float2 v;
                    v.x = rtf32(acc[mt][nt][0 + 2 * half_r] + b0);
                    v.y = rtf32(acc[mt][nt][1 + 2 * half_r] + b1);
                    *reinterpret_cast<float2*>(&C[(size_t)drow * DD + c]) = v;
                }
            }
        }
    } else {
        // highway: acc pair = (proj, gate) for channel col/2; x_old = A
#pragma unroll
        for (int mt = 0; mt < 4; mt++) {
            int r0 = bm + wm + mt * 16 + g;
#pragma unroll
            for (int nt = 0; nt < 4; nt++) {
                int col = bn + wn + nt * 8 + tg * 2;
                int ch = col >> 1;
                float b0 = bias[col], b1 = bias[col + 1];
#pragma unroll
                for (int half_r = 0; half_r < 2; half_r++) {
                    int r = r0 + half_r * 8;
                    float p  = acc[mt][nt][0 + 2 * half_r] + b0;
                    float gt = acc[mt][nt][1 + 2 * half_r] + b1;
                    float xo = A[(size_t)r * DD + ch];
                    float gate = 1.0f / (1.0f + expf(-gt));
                    float v = gate * xo + (1.0f - gate) * fmaxf(p, 0.0f);
                    C[(size_t)r * DD + ch] = (mode == 2) ? rtf32(v) : v;
                }
            }
        }
    }
}

// ---------------------------------------------------------------------------
// Banded window attention, both sides in one launch.
// ---------------------------------------------------------------------------
__global__ void attn_kernel(const float* __restrict__ QKV,
                            float* __restrict__ out0,
                            float* __restrict__ out1) {
    const int t = blockIdx.x * 4 + (threadIdx.x >> 6);
    const int h = threadIdx.x & 63;
    const int side = (t >= MQ) ? 1 : 0;
    const int bi = t - side * MQ;
    const int b = bi / NN;
    const int i = bi % NN;
    const int soff = side * 1536;

    const float4* qv = reinterpret_cast<const float4*>(
        QKV + (size_t)bi * 3072 + soff + h * 8);
    const float4 q0 = qv[0], q1 = qv[1];

    const int j0 = side ? i : (i - WID - 1);

    float sc[WINSZ];
    float mx = -1e30f;
#pragma unroll
    for (int tt = 0; tt < WINSZ; tt++) {
        int j = j0 + tt;
        bool valid = (j >= 0) && (j < NN);
        int jc = min(max(j, 0), NN - 1);
        const float4* kv = reinterpret_cast<const float4*>(
            QKV + ((size_t)(b * NN + jc)) * 3072 + soff + 512 + h * 8);
        float4 k0 = kv[0], k1 = kv[1];
        float s = q0.x * k0.x + q0.y * k0.y + q0.z * k0.z + q0.w * k0.w +
                  q1.x * k1.x + q1.y * k1.y + q1.z * k1.z + q1.w * k1.w;
        s *= 0.35355339059327373f;
        sc[tt] = valid ? s : -1e30f;
        mx = fmaxf(mx, sc[tt]);
    }
    float sum = 0.0f;
#pragma unroll
    for (int tt = 0; tt < WINSZ; tt++) {
        sc[tt] = expf(sc[tt] - mx);
        sum += sc[tt];
    }
    const float inv = 1.0f / sum;

    float4 a0 = make_float4(0.f, 0.f, 0.f, 0.f);
    float4 a1 = make_float4(0.f, 0.f, 0.f, 0.f);
#pragma unroll
    for (int tt = 0; tt < WINSZ; tt++) {
        int j = j0 + tt;
        int jc = min(max(j, 0), NN - 1);
        const float4* vv = reinterpret_cast<const float4*>(
            QKV + ((size_t)(b * NN + jc)) * 3072 + soff + 1024 + h * 8);
        float4 v0 = vv[0], v1 = vv[1];
        float p = sc[tt] * inv;
        a0.x += p * v0.x; a0.y += p * v0.y; a0.z += p * v0.z; a0.w += p * v0.w;
        a1.x += p * v1.x; a1.y += p * v1.y; a1.z += p * v1.z; a1.w += p * v1.w;
    }
    float* out = side ? out1 : out0;
    float4* op = reinterpret_cast<float4*>(out + (size_t)bi * DD + h * 8);
    op[0] = rtf32_4(a0);
    op[1] = rtf32_4(a1);
}

// ---------------------------------------------------------------------------
// Output: last = concat(left, right); tuple (last[None], last) = data twice
// ---------------------------------------------------------------------------
__global__ void write_out_kernel(const float* __restrict__ hl,
                                 const float* __restrict__ hr,
                                 float* __restrict__ out, int out_size) {
    int t = blockIdx.x * blockDim.x + threadIdx.x;
    const int TOT4 = MH * (2 * DD / 4);
    if (t >= TOT4) return;
    int r = t >> 8;
    int c4 = t & 255;
    float4 v = (c4 < 128)
        ? reinterpret_cast<const float4*>(hl)[r * 128 + c4]
        : reinterpret_cast<const float4*>(hr)[r * 128 + (c4 - 128)];
    reinterpret_cast<float4*>(out)[t] = v;
    long long second = (long long)(t + TOT4) * 4 + 3;
    if (second < (long long)out_size)
        reinterpret_cast<float4*>(out)[t + TOT4] = v;
}

// ---------------------------------------------------------------------------
// Launch
// ---------------------------------------------------------------------------
extern "C" void kernel_launch(void* const* d_in, const int* in_sizes, int n_in,
                              void* d_out, int out_size) {
    const float* inputs    = (const float*)d_in[0];
    const float* left_pad  = (const float*)d_in[1];
    const float* right_pad = (const float*)d_in[2];
    const float* l_Wqkv    = (const float*)d_in[3];
    const float* l_bqkv    = (const float*)d_in[4];
    const float* l_Wo      = (const float*)d_in[5];
    const float* l_bo      = (const float*)d_in[6];
    const float* r_Wqkv    = (const float*)d_in[7];
    const float* r_bqkv    = (const float*)d_in[8];
    const float* r_Wo      = (const float*)d_in[9];
    const float* r_bo      = (const float*)d_in[10];
    const float* lhw_W     = (const float*)d_in[11];
    const float* lhw_b     = (const float*)d_in[12];
    const float* rhw_W     = (const float*)d_in[13];
    const float* rhw_b     = (const float*)d_in[14];
    float* out = (float*)d_out;

    float *pX, *pQKV, *pATT0, *pATT1, *pHX0, *pHX1, *pHY0, *pHY1, *pWC, *pB;
    cudaGetSymbolAddress((void**)&pX,    g_X);
    cudaGetSymbolAddress((void**)&pQKV,  g_QKVcat);
    cudaGetSymbolAddress((void**)&pATT0, g_ATT0);
    cudaGetSymbolAddress((void**)&pATT1, g_ATT1);
    cudaGetSymbolAddress((void**)&pHX0,  g_HX0);
    cudaGetSymbolAddress((void**)&pHX1,  g_HX1);
    cudaGetSymbolAddress((void**)&pHY0,  g_HY0);
    cudaGetSymbolAddress((void**)&pHY1,  g_HY1);
    cudaGetSymbolAddress((void**)&pWC,   g_WC);
    cudaGetSymbolAddress((void**)&pB,    g_B);

    cudaFuncSetAttribute(gemm_fused_kernel,
                         cudaFuncAttributeMaxDynamicSharedMemorySize, DYN_SMEM);

    // 0) weights + biases (tf32 / permuted)
    convert_weights_kernel<<<(1048576 + 255) / 256, 256>>>(
        l_Wqkv, r_Wqkv, l_Wo, r_Wo, lhw_W, rhw_W, pWC);
    bias_cat_kernel<<<(7168 + 255) / 256, 256>>>(l_bqkv, r_bqkv, lhw_b, rhw_b, pB);

    // 1) padded, rounded input
    pad_kernel<<<(MQ * (DD / 4) + 255) / 256, 256>>>(inputs, left_pad, right_pad, pX);

    // 2) merged QKV GEMM: [4352,512] @ [3072,512]^T (both sides)
    gemm_fused_kernel<<<dim3(3072 / 128, MQ / 128, 1), 256, DYN_SMEM>>>(
        pX, pX, pWC, pWC, pB, pB, pQKV, pQKV, 3072, 0);

    // 3) windowed attention, both sides
    attn_kernel<<<(2 * MQ) / 4, 256>>>(pQKV, pATT0, pATT1);

    // 4) Wo GEMM + slice, both sides via z
    gemm_fused_kernel<<<dim3(DD / 128, MQ / 128, 2), 256, DYN_SMEM>>>(
        pATT0, pATT1, pWC + 1572864, pWC + 1835008, l_bo, r_bo,
        pHX0, pHX1, DD, 1);

    // 5) highway layer 0: HX -> HY (rounded)
    gemm_fused_kernel<<<dim3(1024 / 128, MH / 128, 2), 256, DYN_SMEM>>>(
        pHX0, pHX1, pWC + 2097152, pWC + 3145728,
        pB + 3072, pB + 3072 + 2048, pHY0, pHY1, 1024, 2);

    // 6) highway layer 1: HY -> HX (unrounded)
    gemm_fused_kernel<<<dim3(1024 / 128, MH / 128, 2), 256, DYN_SMEM>>>(
        pHY0, pHY1, pWC + 2097152 + 524288, pWC + 3145728 + 524288,
        pB + 3072 + 1024, pB + 3072 + 2048 + 1024, pHX0, pHX1, 1024, 3);

    // 7) final concat + duplicate write
    write_out_kernel<<<(MH * (2 * DD / 4) + 255) / 256, 256>>>(
        pHX0, pHX1, out, out_size);
}

// round 11
// speedup vs baseline: 5.7310x; 1.6669x over previous
#include <cuda_runtime.h>
#include <cuda_fp16.h>
#include <cstdint>
#include <math.h>

// ---------------------------------------------------------------------------
// Problem constants
// ---------------------------------------------------------------------------
#define BB    8
#define SS    512
#define DD    512
#define WID   16
#define NN    (SS + 2 * WID)      // 544
#define MQ    (BB * NN)           // 4352
#define MH    (BB * SS)           // 4096
#define KDIM  512
#define WINSZ (WID + 2)           // 18

// GEMM tiling: 128x128 tile, BK=32 (fp16), 3-stage cp.async ring
#define STRH     40                         // smem row stride in halfs
#define A_BYTES  (128 * STRH * 2)           // 10240
#define STG_BYTES (2 * A_BYTES)             // 20480 (A tile + W tile)
#define NSTG     3
#define DYN_SMEM (NSTG * STG_BYTES)         // 61440

// ---------------------------------------------------------------------------
// Scratch (static device memory; allocation is forbidden)
// ---------------------------------------------------------------------------
__device__ __half g_X[MQ * DD];
__device__ __half g_QKVcat[MQ * 3072];
__device__ __half g_ATT0[MQ * DD];
__device__ __half g_ATT1[MQ * DD];
__device__ __half g_HX0[MH * DD];
__device__ __half g_HX1[MH * DD];
__device__ __half g_HY0[MH * DD];
__device__ __half g_HY1[MH * DD];
__device__ float  g_FO0[MH * DD];       // final highway output (fp32)
__device__ float  g_FO1[MH * DD];
// fp16 weights, packed (half units):
//  [0]        l_Wqkv  1536*512
//  [786432]   r_Wqkv
//  [1572864]  l_Wo     512*512
//  [1835008]  r_Wo
//  [2097152]  lhw_W   2*1024*512  (rows interleaved: 2c=proj_c, 2c+1=gate_c)
//  [3145728]  rhw_W
__device__ __half g_WC[4194304];
// fp32 biases: [0..3071] qkv cat (l then r); [3072..7167] hw interleaved
__device__ float g_B[7168];

// ---------------------------------------------------------------------------
// Convert weights to fp16, packed into g_WC (t indexes float4 of source = 4 halfs out)
// ---------------------------------------------------------------------------
__global__ void convert_weights_kernel(const float* __restrict__ lqkv,
                                       const float* __restrict__ rqkv,
                                       const float* __restrict__ lwo,
                                       const float* __restrict__ rwo,
                                       const float* __restrict__ lhw,
                                       const float* __restrict__ rhw,
                                       __half* __restrict__ out) {
    int t = blockIdx.x * blockDim.x + threadIdx.x;
    if (t >= 1048576) return;
    const float* src;
    int loc;
    if (t < 196608)      { src = lqkv; loc = t; }
    else if (t < 393216) { src = rqkv; loc = t - 196608; }
    else if (t < 458752) { src = lwo;  loc = t - 393216; }
    else if (t < 524288) { src = rwo;  loc = t - 458752; }
    else {
        int u = t - 524288;
        int side  = u / 262144;
        int v     = u % 262144;
        int layer = v / 131072;
        int w     = v % 131072;
        int j     = w / 128;           // dest row (interleaved proj/gate)
        int c4    = w % 128;
        int srow  = (j & 1) ? (512 + (j >> 1)) : (j >> 1);
        src = side ? rhw : lhw;
        loc = layer * 131072 + srow * 128 + c4;
    }
    float4 v = reinterpret_cast<const float4*>(src)[loc];
    __half2 h0 = __floats2half2_rn(v.x, v.y);
    __half2 h1 = __floats2half2_rn(v.z, v.w);
    uint2 pk = make_uint2(*(uint32_t*)&h0, *(uint32_t*)&h1);
    *reinterpret_cast<uint2*>(out + (size_t)t * 4) = pk;
}

__global__ void bias_cat_kernel(const float* __restrict__ lbq,
                                const float* __restrict__ rbq,
                                const float* __restrict__ lhb,
                                const float* __restrict__ rhb,
                                float* __restrict__ B) {
    int t = blockIdx.x * blockDim.x + threadIdx.x;
    if (t >= 7168) return;
    if (t < 1536)       B[t] = lbq[t];
    else if (t < 3072)  B[t] = rbq[t - 1536];
    else {
        int u = t - 3072;
        int side  = u >> 11;
        int layer = (u >> 10) & 1;
        int j     = u & 1023;
        int c     = j >> 1;
        int srcj  = (j & 1) ? (512 + c) : c;
        const float* hb = side ? rhb : lhb;
        B[t] = hb[layer * 1024 + srcj];
    }
}

// ---------------------------------------------------------------------------
// Padded input -> fp16
// ---------------------------------------------------------------------------
__global__ void pad_kernel(const float* __restrict__ inp,
                           const float* __restrict__ lp,
                           const float* __restrict__ rp,
                           __half* __restrict__ X) {
    int t = blockIdx.x * blockDim.x + threadIdx.x;     // float4 index
    const int TOT = MQ * (DD / 4);
    if (t >= TOT) return;
    int row = t / (DD / 4);
    int c4  = t % (DD / 4);
    int b = row / NN;
    int n = row % NN;
    float4 v;
    if (n < WID) {
        v = reinterpret_cast<const float4*>(lp)[n * (DD / 4) + c4];
    } else if (n >= WID + SS) {
        v = reinterpret_cast<const float4*>(rp)[(n - WID - SS) * (DD / 4) + c4];
    } else {
        v = reinterpret_cast<const float4*>(inp)[((size_t)b * SS + (n - WID)) * (DD / 4) + c4];
    }
    __half2 h0 = __floats2half2_rn(v.x, v.y);
    __half2 h1 = __floats2half2_rn(v.z, v.w);
    uint2 pk = make_uint2(*(uint32_t*)&h0, *(uint32_t*)&h1);
    *reinterpret_cast<uint2*>(X + (size_t)t * 4) = pk;
}

// ---------------------------------------------------------------------------
// FP16 mma.sync GEMM: C[M, Nt] = A[M,512]h @ W[Nt,512]h^T (f32 accum),
// fused epilogues. 128x128 tile, BK=32, 8 warps (64x32), ldmatrix,
// 3-stage cp.async ring, ONE __syncthreads per K-step.
//   mode 0: C(half) = acc + bias                  (stride Nt)
//   mode 1: Wo + row-slice [WID,WID+SS) -> C(half, stride 512)
//   mode 2: highway (interleaved proj/gate cols) -> C(half, stride 512)
//   mode 3: highway -> C(float, stride 512)
// blockIdx.z selects side.
// ---------------------------------------------------------------------------
__global__ __launch_bounds__(256, 2) void gemm_fused_kernel(
    const __half* __restrict__ A0, const __half* __restrict__ A1,
    const __half* __restrict__ W0, const __half* __restrict__ W1,
    const float* __restrict__ B0, const float* __restrict__ B1,
    void* __restrict__ C0, void* __restrict__ C1,
    int Nt, int mode) {
    extern __shared__ char dsm[];

    const int z = blockIdx.z;
    const __half* A = z ? A1 : A0;
    const __half* W = z ? W1 : W0;
    const float* bias = z ? B1 : B0;
    void* C = z ? C1 : C0;

    const int bm = blockIdx.y * 128;
    const int bn = blockIdx.x * 128;
    const int tid = threadIdx.x;
    const int lane = tid & 31;
    const int wrp = tid >> 5;
    const int wm = (wrp & 1) * 64;     // warp m offset
    const int wn = (wrp >> 1) * 32;    // warp n offset
    const int g  = lane >> 2;          // epilogue row within 8
    const int tg = lane & 3;

    const uint32_t smemBase = (uint32_t)__cvta_generic_to_shared(dsm);

    // ldmatrix provider byte offsets
    const uint32_t aOff =
        ((wm + (lane & 15)) * STRH + (lane >> 4) * 8) * 2;
    const uint32_t bOff =
        ((wn + ((lane >> 4) & 1) * 8 + (lane & 7)) * STRH + ((lane >> 3) & 1) * 8) * 2;

    float acc[4][4][4];
#pragma unroll
    for (int mt = 0; mt < 4; mt++)
#pragma unroll
        for (int nt = 0; nt < 4; nt++)
#pragma unroll
            for (int r = 0; r < 4; r++) acc[mt][nt][r] = 0.0f;

    // global->smem: per stage 1024 16B-chunks (A 512 + W 512), 4 per thread
    auto issue = [&](int s, int k0) {
        uint32_t base = smemBase + s * STG_BYTES;
#pragma unroll
        for (int i = 0; i < 2; i++) {
            int id = tid + (i << 8);
            int r = id >> 2, c = id & 3;
            uint32_t dst = base + (r * STRH + c * 8) * 2;
            const __half* src = A + (size_t)(bm + r) * KDIM + k0 + c * 8;
            asm volatile("cp.async.cg.shared.global [%0], [%1], 16;"
                         :: "r"(dst), "l"(src));
        }
#pragma unroll
        for (int i = 0; i < 2; i++) {
            int id = tid + (i << 8);
            int r = id >> 2, c = id & 3;
            uint32_t dst = base + A_BYTES + (r * STRH + c * 8) * 2;
            const __half* src = W + (size_t)(bn + r) * KDIM + k0 + c * 8;
            asm volatile("cp.async.cg.shared.global [%0], [%1], 16;"
                         :: "r"(dst), "l"(src));
        }
        asm volatile("cp.async.commit_group;");
    };

    auto compute = [&](int s) {
        const uint32_t aPtr = smemBase + s * STG_BYTES + aOff;
        const uint32_t wPtr = smemBase + s * STG_BYTES + A_BYTES + bOff;
#pragma unroll
        for (int kc = 0; kc < 2; kc++) {           // two k16 chunks in BK=32
            uint32_t a[4][4], b[4][2];
#pragma unroll
            for (int mt = 0; mt < 4; mt++) {
                uint32_t addr = aPtr + mt * (16 * STRH * 2) + kc * 32;
                asm volatile(
                    "ldmatrix.sync.aligned.m8n8.x4.shared.b16 {%0,%1,%2,%3}, [%4];"
                    : "=r"(a[mt][0]), "=r"(a[mt][1]), "=r"(a[mt][2]),
                      "=r"(a[mt][3])
                    : "r"(addr));
            }
#pragma unroll
            for (int ntp = 0; ntp < 2; ntp++) {
                uint32_t addr = wPtr + ntp * (16 * STRH * 2) + kc * 32;
                asm volatile(
                    "ldmatrix.sync.aligned.m8n8.x4.shared.b16 {%0,%1,%2,%3}, [%4];"
                    : "=r"(b[2 * ntp][0]), "=r"(b[2 * ntp][1]),
                      "=r"(b[2 * ntp + 1][0]), "=r"(b[2 * ntp + 1][1])
                    : "r"(addr));
            }
#pragma unroll
            for (int mt = 0; mt < 4; mt++)
#pragma unroll
                for (int nt = 0; nt < 4; nt++)
                    asm volatile(
                        "mma.sync.aligned.m16n8k16.row.col.f32.f16.f16.f32 "
                        "{%0,%1,%2,%3},{%4,%5,%6,%7},{%8,%9},{%0,%1,%2,%3};"
                        : "+f"(acc[mt][nt][0]), "+f"(acc[mt][nt][1]),
                          "+f"(acc[mt][nt][2]), "+f"(acc[mt][nt][3])
                        : "r"(a[mt][0]), "r"(a[mt][1]), "r"(a[mt][2]),
                          "r"(a[mt][3]), "r"(b[nt][0]), "r"(b[nt][1]));
        }
    };

    const int NIT = KDIM / 32;   // 16
    issue(0, 0);
    issue(1, 32);
    for (int it = 0; it < NIT; it++) {
        if (it < NIT - 2)
            asm volatile("cp.async.wait_group 1;");
        else
            asm volatile("cp.async.wait_group 0;");
        __syncthreads();
        if (it + 2 < NIT) issue((it + 2) % NSTG, (it + 2) * 32);
        compute(it % NSTG);
    }

    // ---------------- epilogues ----------------
    if (mode == 0) {
        __half* Ch = (__half*)C;
#pragma unroll
        for (int mt = 0; mt < 4; mt++) {
            int r0 = bm + wm + mt * 16 + g;
#pragma unroll
            for (int nt = 0; nt < 4; nt++) {
                int c = bn + wn + nt * 8 + tg * 2;
                float b0 = bias[c], b1 = bias[c + 1];
                __half2 v0 = __floats2half2_rn(acc[mt][nt][0] + b0,
                                               acc[mt][nt][1] + b1);
                __half2 v1 = __floats2half2_rn(acc[mt][nt][2] + b0,
                                               acc[mt][nt][3] + b1);
                *reinterpret_cast<__half2*>(&Ch[(size_t)r0 * Nt + c]) = v0;
                *reinterpret_cast<__half2*>(&Ch[(size_t)(r0 + 8) * Nt + c]) = v1;
            }
        }
    } else if (mode == 1) {
        // Wo + slice: row r -> (b, n); keep n in [WID, WID+SS); half out
        __half* Ch = (__half*)C;
#pragma unroll
        for (int mt = 0; mt < 4; mt++) {
            int r0 = bm + wm + mt * 16 + g;
#pragma unroll
            for (int half_r = 0; half_r < 2; half_r++) {
                int r = r0 + half_r * 8;
                int b = r / NN;
                int n = r % NN;
                if (n < WID || n >= WID + SS) continue;
                int drow = b * SS + (n - WID);
#pragma unroll
                for (int nt = 0; nt < 4; nt++) {
                    int c = bn + wn + nt * 8 + tg * 2;
                    float b0 = bias[c], b1 = bias[c + 1];
                    __half2 v = __floats2half2_rn(
                        acc[mt][nt][0 + 2 * half_r] + b0,
                        acc[mt][nt][1 + 2 * half_r] + b1);
                    *reinterpret_cast<__half2*>(&Ch[(size_t)drow * DD + c]) = v;
                }
            }
        }
    } else {
        // highway: acc pair = (proj, gate) for channel col/2; x_old = A (half)
#pragma unroll
        for (int mt = 0; mt < 4; mt++) {
            int r0 = bm + wm + mt * 16 + g;
#pragma unroll
            for (int nt = 0; nt < 4; nt++) {
                int col = bn + wn + nt * 8 + tg * 2;
                int ch = col >> 1;
                float b0 = bias[col], b1 = bias[col + 1];
#pragma unroll
                for (int half_r = 0; half_r < 2; half_r++) {
                    int r = r0 + half_r * 8;
                    float p  = acc[mt][nt][0 + 2 * half_r] + b0;
                    float gt = acc[mt][nt][1 + 2 * half_r] + b1;
                    float xo = __half2float(A[(size_t)r * DD + ch]);
                    float gate = 1.0f / (1.0f + expf(-gt));
                    float v = gate * xo + (1.0f - gate) * fmaxf(p, 0.0f);
                    if (mode == 2)
                        ((__half*)C)[(size_t)r * DD + ch] = __float2half_rn(v);
                    else
                        ((float*)C)[(size_t)r * DD + ch] = v;
                }
            }
        }
    }
}

// ---------------------------------------------------------------------------
// Banded window attention (fp16 QKV, fp32 math), both sides in one launch.
// ---------------------------------------------------------------------------
__device__ __forceinline__ float dot8h(const __half2* a, const __half2* b) {
    float s = 0.0f;
#pragma unroll
    for (int i = 0; i < 4; i++) {
        float2 fa = __half22float2(a[i]);
        float2 fb = __half22float2(b[i]);
        s += fa.x * fb.x + fa.y * fb.y;
    }
    return s;
}

__global__ void attn_kernel(const __half* __restrict__ QKV,
                            __half* __restrict__ out0,
                            __half* __restrict__ out1) {
    const int t = blockIdx.x * 4 + (threadIdx.x >> 6);
    const int h = threadIdx.x & 63;
    const int side = (t >= MQ) ? 1 : 0;
    const int bi = t - side * MQ;
    const int b = bi / NN;
    const int i = bi % NN;
    const int soff = side * 1536;

    __half2 q[4];
    *reinterpret_cast<uint4*>(q) = *reinterpret_cast<const uint4*>(
        QKV + (size_t)bi * 3072 + soff + h * 8);

    const int j0 = side ? i : (i - WID - 1);

    float sc[WINSZ];
    float mx = -1e30f;
#pragma unroll
    for (int tt = 0; tt < WINSZ; tt++) {
        int j = j0 + tt;
        bool valid = (j >= 0) && (j < NN);
        int jc = min(max(j, 0), NN - 1);
        __half2 k[4];
        *reinterpret_cast<uint4*>(k) = *reinterpret_cast<const uint4*>(
            QKV + ((size_t)(b * NN + jc)) * 3072 + soff + 512 + h * 8);
        float s = dot8h(q, k) * 0.35355339059327373f;
        sc[tt] = valid ? s : -1e30f;
        mx = fmaxf(mx, sc[tt]);
    }
    float sum = 0.0f;
#pragma unroll
    for (int tt = 0; tt < WINSZ; tt++) {
        sc[tt] = expf(sc[tt] - mx);
        sum += sc[tt];
    }
    const float inv = 1.0f / sum;

    float a[8] = {0.f, 0.f, 0.f, 0.f, 0.f, 0.f, 0.f, 0.f};
#pragma unroll
    for (int tt = 0; tt < WINSZ; tt++) {
        int j = j0 + tt;
        int jc = min(max(j, 0), NN - 1);
        __half2 v[4];
        *reinterpret_cast<uint4*>(v) = *reinterpret_cast<const uint4*>(
            QKV + ((size_t)(b * NN + jc)) * 3072 + soff + 1024 + h * 8);
        float p = sc[tt] * inv;
#pragma unroll
        for (int e = 0; e < 4; e++) {
            float2 fv = __half22float2(v[e]);
            a[2 * e]     += p * fv.x;
            a[2 * e + 1] += p * fv.y;
        }
    }
    __half* out = side ? out1 : out0;
    __half2 o[4];
#pragma unroll
    for (int e = 0; e < 4; e++) o[e] = __floats2half2_rn(a[2 * e], a[2 * e + 1]);
    *reinterpret_cast<uint4*>(out + (size_t)bi * DD + h * 8) =
        *reinterpret_cast<uint4*>(o);
}

// ---------------------------------------------------------------------------
// Output: last = concat(left, right); tuple (last[None], last) = data twice
// ---------------------------------------------------------------------------
__global__ void write_out_kernel(const float* __restrict__ hl,
                                 const float* __restrict__ hr,
                                 float* __restrict__ out, int out_size) {
    int t = blockIdx.x * blockDim.x + threadIdx.x;
    const int TOT4 = MH * (2 * DD / 4);
    if (t >= TOT4) return;
    int r = t >> 8;
    int c4 = t & 255;
    float4 v = (c4 < 128)
        ? reinterpret_cast<const float4*>(hl)[r * 128 + c4]
        : reinterpret_cast<const float4*>(hr)[r * 128 + (c4 - 128)];
    reinterpret_cast<float4*>(out)[t] = v;
    long long second = (long long)(t + TOT4) * 4 + 3;
    if (second < (long long)out_size)
        reinterpret_cast<float4*>(out)[t + TOT4] = v;
}

// ---------------------------------------------------------------------------
// Launch
// ---------------------------------------------------------------------------
extern "C" void kernel_launch(void* const* d_in, const int* in_sizes, int n_in,
                              void* d_out, int out_size) {
    const float* inputs    = (const float*)d_in[0];
    const float* left_pad  = (const float*)d_in[1];
    const float* right_pad = (const float*)d_in[2];
    const float* l_Wqkv    = (const float*)d_in[3];
    const float* l_bqkv    = (const float*)d_in[4];
    const float* l_Wo      = (const float*)d_in[5];
    const float* l_bo      = (const float*)d_in[6];
    const float* r_Wqkv    = (const float*)d_in[7];
    const float* r_bqkv    = (const float*)d_in[8];
    const float* r_Wo      = (const float*)d_in[9];
    const float* r_bo      = (const float*)d_in[10];
    const float* lhw_W     = (const float*)d_in[11];
    const float* lhw_b     = (const float*)d_in[12];
    const float* rhw_W     = (const float*)d_in[13];
    const float* rhw_b     = (const float*)d_in[14];
    float* out = (float*)d_out;

    __half *pX, *pQKV, *pATT0, *pATT1, *pHX0, *pHX1, *pHY0, *pHY1, *pWC;
    float *pFO0, *pFO1, *pB;
    cudaGetSymbolAddress((void**)&pX,    g_X);
    cudaGetSymbolAddress((void**)&pQKV,  g_QKVcat);
    cudaGetSymbolAddress((void**)&pATT0, g_ATT0);
    cudaGetSymbolAddress((void**)&pATT1, g_ATT1);
    cudaGetSymbolAddress((void**)&pHX0,  g_HX0);
    cudaGetSymbolAddress((void**)&pHX1,  g_HX1);
    cudaGetSymbolAddress((void**)&pHY0,  g_HY0);
    cudaGetSymbolAddress((void**)&pHY1,  g_HY1);
    cudaGetSymbolAddress((void**)&pFO0,  g_FO0);
    cudaGetSymbolAddress((void**)&pFO1,  g_FO1);
    cudaGetSymbolAddress((void**)&pWC,   g_WC);
    cudaGetSymbolAddress((void**)&pB,    g_B);

    cudaFuncSetAttribute(gemm_fused_kernel,
                         cudaFuncAttributeMaxDynamicSharedMemorySize, DYN_SMEM);

    // 0) weights + biases (fp16 / permuted)
    convert_weights_kernel<<<(1048576 + 255) / 256, 256>>>(
        l_Wqkv, r_Wqkv, l_Wo, r_Wo, lhw_W, rhw_W, pWC);
    bias_cat_kernel<<<(7168 + 255) / 256, 256>>>(l_bqkv, r_bqkv, lhw_b, rhw_b, pB);

    // 1) padded fp16 input
    pad_kernel<<<(MQ * (DD / 4) + 255) / 256, 256>>>(inputs, left_pad, right_pad, pX);

    // 2) merged QKV GEMM: [4352,512] @ [3072,512]^T (both sides)
    gemm_fused_kernel<<<dim3(3072 / 128, MQ / 128, 1), 256, DYN_SMEM>>>(
        pX, pX, pWC, pWC, pB, pB, pQKV, pQKV, 3072, 0);

    // 3) windowed attention, both sides
    attn_kernel<<<(2 * MQ) / 4, 256>>>(pQKV, pATT0, pATT1);

    // 4) Wo GEMM + slice, both sides via z
    gemm_fused_kernel<<<dim3(DD / 128, MQ / 128, 2), 256, DYN_SMEM>>>(
        pATT0, pATT1, pWC + 1572864, pWC + 1835008, l_bo, r_bo,
        pHX0, pHX1, DD, 1);

    // 5) highway layer 0: HX -> HY (half)
    gemm_fused_kernel<<<dim3(1024 / 128, MH / 128, 2), 256, DYN_SMEM>>>(
        pHX0, pHX1, pWC + 2097152, pWC + 3145728,
        pB + 3072, pB + 3072 + 2048, pHY0, pHY1, 1024, 2);

    // 6) highway layer 1: HY -> FO (fp32)
    gemm_fused_kernel<<<dim3(1024 / 128, MH / 128, 2), 256, DYN_SMEM>>>(
        pHY0, pHY1, pWC + 2097152 + 524288, pWC + 3145728 + 524288,
        pB + 3072 + 1024, pB + 3072 + 2048 + 1024, pFO0, pFO1, 1024, 3);

    // 7) final concat + duplicate write
    write_out_kernel<<<(MH * (2 * DD / 4) + 255) / 256, 256>>>(
        pFO0, pFO1, out, out_size);
}